// round 2
// baseline (speedup 1.0000x reference)
#include <cuda_runtime.h>
#include <cuda_fp16.h>
#include <math.h>

#define Pn 128
#define Ln 512
#define En 256
#define Fn 128
#define Tn 509
#define WROW 136   // padded halves per W_hh row (272 B: conflict-free LDS.128)

// ---------------- scratch (device globals; allocation is forbidden) ----------
__device__ float g_xs [(size_t)Pn * Tn * Fn];     // conv output [p][t][f]   (~33 MB)
__device__ float g_gx [(size_t)Pn * Tn * 1024];   // input gates [p*T][fwd512|bwd512] (~267 MB)
__device__ float g_ctx[Pn * En];                  // BiLSTM context [p][2H]
__device__ float g_cwT[En * 3 * Fn];              // conv_w transposed [(e*3+k)][f]
__device__ float g_d1wT[512 * 256];               // d1_w transposed [k][e]
__device__ float g_score[Pn];
__device__ float g_u[En];

// ---------------- helpers ----------------------------------------------------
__device__ __forceinline__ float sigf(float x) {
    return __fdividef(1.f, 1.f + __expf(-x));
}
__device__ __forceinline__ float tanh_(float x) {
    return __fdividef(2.f, 1.f + __expf(-2.f * x)) - 1.f;
}
union UH { unsigned int u; __half2 h; };
__device__ __forceinline__ __half2 as_h2(unsigned int x) { UH v; v.u = x; return v.h; }

// ---------------- prep: weight transposes ------------------------------------
__global__ void prep_kernel(const float* __restrict__ conv_w,
                            const float* __restrict__ d1w) {
    int idx = blockIdx.x * blockDim.x + threadIdx.x;
    if (idx < En * 3 * Fn) {                       // 98304: cwT[(e*3+k)*128+f]
        int f = idx & 127, ek = idx >> 7;
        g_cwT[idx] = conv_w[(size_t)f * (En * 3) + ek];
    } else {
        int j = idx - En * 3 * Fn;
        if (j < 512 * 256) {                       // 131072: d1wT[k*256+e]
            int e = j & 255, k = j >> 8;
            g_d1wT[j] = d1w[(size_t)e * 512 + k];
        }
    }
}

__global__ void init_u_kernel(const int* __restrict__ q,
                              const float* __restrict__ embB) {
    int t = threadIdx.x;              // 256 threads
    g_u[t] = embB[(size_t)q[0] * En + t];
}

// ---------------- phase A: embed + conv + relu + maxpool ----------------------
// grid (16 tiles, 128 paths), 128 threads (thread = filter f)
__global__ void __launch_bounds__(128) conv_kernel(const int* __restrict__ path,
                                                   const float* __restrict__ embA,
                                                   const float* __restrict__ conv_b) {
    __shared__ float esh[35 * En];   // 35 token embeddings (35 KB)
    int p  = blockIdx.y;
    int l0 = blockIdx.x * 32;
    int f  = threadIdx.x;

    for (int i = 0; i < 35; i++) {
        int lt = l0 + i;
        float2 v = make_float2(0.f, 0.f);
        if (lt < Ln) {
            int tok = path[p * Ln + lt];
            v = *(const float2*)(embA + (size_t)tok * En + f * 2);
        }
        *(float2*)(esh + i * En + f * 2) = v;
    }
    __syncthreads();

    float acc[33];
#pragma unroll
    for (int l = 0; l < 33; l++) acc[l] = 0.f;

    for (int e = 0; e < En; e++) {
        float w0 = g_cwT[(e * 3 + 0) * Fn + f];
        float w1 = g_cwT[(e * 3 + 1) * Fn + f];
        float w2 = g_cwT[(e * 3 + 2) * Fn + f];
        float e0 = esh[e], e1 = esh[En + e];
#pragma unroll
        for (int l = 0; l < 33; l++) {
            float e2 = esh[(l + 2) * En + e];
            acc[l] += w0 * e0 + w1 * e1 + w2 * e2;
            e0 = e1; e1 = e2;
        }
    }

    float b = conv_b[f];
#pragma unroll
    for (int l = 0; l < 32; l++) {
        int t = l0 + l;
        if (t < Tn) {
            float m = fmaxf(acc[l], acc[l + 1]);             // maxpool(2, stride 1)
            g_xs[((size_t)p * Tn + t) * Fn + f] = fmaxf(m + b, 0.f);  // relu(conv+b)
        }
    }
}

// ---------------- phase B: input-gate GEMM -----------------------------------
// gx[row][col] = xs[row][:] . W[col][:] + bias[col];  rows = 65152, cols = 1024
// grid (509, 8), block 256; 128x128 tiles, K=128 in one shot; 8x8 microtiles
__global__ void __launch_bounds__(256) gemm_kernel(
        const float* __restrict__ wihf, const float* __restrict__ wihb,
        const float* __restrict__ bihf, const float* __restrict__ bhhf,
        const float* __restrict__ bihb, const float* __restrict__ bhhb) {
    extern __shared__ float smf[];
    float* As = smf;                 // [k=128][r=132 padded]
    float* Bs = smf + 128 * 132;     // [k=128][c=132 padded]
    __shared__ float bias_s[128];

    int row0 = blockIdx.x * 128;
    int by   = blockIdx.y;
    int tid  = threadIdx.x;

    const float* Bp = (by < 4) ? (wihf + (size_t)by * 128 * 128)
                               : (wihb + (size_t)(by - 4) * 128 * 128);
    if (tid < 128) {
        bias_s[tid] = (by < 4) ? (bihf[by * 128 + tid] + bhhf[by * 128 + tid])
                               : (bihb[(by - 4) * 128 + tid] + bhhb[(by - 4) * 128 + tid]);
    }
    for (int idx = tid; idx < 16384; idx += 256) {
        int r = idx >> 7, k = idx & 127;
        As[k * 132 + r] = g_xs[(size_t)(row0 + r) * 128 + k];
        Bs[k * 132 + r] = Bp[idx];
    }
    __syncthreads();

    int tx = tid & 15, ty = tid >> 4;
    float acc[8][8];
#pragma unroll
    for (int i = 0; i < 8; i++)
#pragma unroll
        for (int j = 0; j < 8; j++) acc[i][j] = 0.f;

#pragma unroll 4
    for (int k = 0; k < 128; k++) {
        float4 a0 = *(const float4*)(As + k * 132 + ty * 8);
        float4 a1 = *(const float4*)(As + k * 132 + ty * 8 + 4);
        float4 b0 = *(const float4*)(Bs + k * 132 + tx * 8);
        float4 b1 = *(const float4*)(Bs + k * 132 + tx * 8 + 4);
        float av[8] = {a0.x, a0.y, a0.z, a0.w, a1.x, a1.y, a1.z, a1.w};
        float bv[8] = {b0.x, b0.y, b0.z, b0.w, b1.x, b1.y, b1.z, b1.w};
#pragma unroll
        for (int i = 0; i < 8; i++)
#pragma unroll
            for (int j = 0; j < 8; j++) acc[i][j] += av[i] * bv[j];
    }

#pragma unroll
    for (int i = 0; i < 8; i++) {
        size_t rp = (size_t)(row0 + ty * 8 + i) * 1024 + by * 128 + tx * 8;
#pragma unroll
        for (int j = 0; j < 8; j++) g_gx[rp + j] = acc[i][j] + bias_s[tx * 8 + j];
    }
}

// ---------------- phase C: LSTM recurrence -----------------------------------
// 128 CTAs: bid = (pair<<1)|dir; 256 threads: seq = tid>>7, gb = tid&127
// Thread owns hidden unit gb of sequence (path = pair*2+seq): computes gates
// i,f,g,o for that unit (rows gb, gb+128, gb+256, gb+384 of W_hh).
__global__ void __launch_bounds__(256) lstm_kernel(const float* __restrict__ whhf,
                                                   const float* __restrict__ whhb) {
    extern __shared__ char smraw[];
    __half* wsh = (__half*)smraw;                         // 512 x WROW halves
    __half* hsh = (__half*)(smraw + 512 * WROW * 2);      // 2 x 128 halves

    int bid  = blockIdx.x;
    int dir  = bid & 1;
    int pair = bid >> 1;
    int tid  = threadIdx.x;
    int seq  = tid >> 7;
    int gb   = tid & 127;
    int path = pair * 2 + seq;

    const float* whh = dir ? whhb : whhf;
    for (int idx = tid; idx < 512 * 128; idx += 256) {
        int r = idx >> 7, k = idx & 127;
        wsh[r * WROW + k] = __float2half(whh[idx]);
    }
    hsh[tid] = __float2half(0.f);   // 256 = both seqs' h
    __syncthreads();

    const uint4* wi4 = (const uint4*)(wsh + (size_t)(gb      ) * WROW);
    const uint4* wf4 = (const uint4*)(wsh + (size_t)(gb + 128) * WROW);
    const uint4* wg4 = (const uint4*)(wsh + (size_t)(gb + 256) * WROW);
    const uint4* wo4 = (const uint4*)(wsh + (size_t)(gb + 384) * WROW);
    const uint4* h4  = (const uint4*)(hsh + seq * 128);

    const float* gxbase = g_gx + (size_t)path * Tn * 1024 + dir * 512 + gb;

    float c = 0.f, hval = 0.f;
    const __half2 z = __float2half2_rn(0.f);

    for (int s = 0; s < Tn; s++) {
        int tt = dir ? (Tn - 1 - s) : s;
        const float* gxr = gxbase + (size_t)tt * 1024;
        float gxi = gxr[0], gxf = gxr[128], gxg = gxr[256], gxo = gxr[384];

        __half2 ai = z, af = z, ag = z, ao = z;
        float fi = 0.f, ff = 0.f, fg = 0.f, fo = 0.f;
#pragma unroll
        for (int o = 0; o < 16; o++) {
            uint4 hv  = h4[o];
            uint4 wiv = wi4[o], wfv = wf4[o], wgv = wg4[o], wov = wo4[o];
            __half2 h0 = as_h2(hv.x), h1 = as_h2(hv.y);
            __half2 h2v = as_h2(hv.z), h3 = as_h2(hv.w);
            ai = __hfma2(as_h2(wiv.x), h0, ai); ai = __hfma2(as_h2(wiv.y), h1, ai);
            ai = __hfma2(as_h2(wiv.z), h2v, ai); ai = __hfma2(as_h2(wiv.w), h3, ai);
            af = __hfma2(as_h2(wfv.x), h0, af); af = __hfma2(as_h2(wfv.y), h1, af);
            af = __hfma2(as_h2(wfv.z), h2v, af); af = __hfma2(as_h2(wfv.w), h3, af);
            ag = __hfma2(as_h2(wgv.x), h0, ag); ag = __hfma2(as_h2(wgv.y), h1, ag);
            ag = __hfma2(as_h2(wgv.z), h2v, ag); ag = __hfma2(as_h2(wgv.w), h3, ag);
            ao = __hfma2(as_h2(wov.x), h0, ao); ao = __hfma2(as_h2(wov.y), h1, ao);
            ao = __hfma2(as_h2(wov.z), h2v, ao); ao = __hfma2(as_h2(wov.w), h3, ao);
            if ((o & 3) == 3) {                 // flush to fp32 every 4 octets
                float2 t;
                t = __half22float2(ai); fi += t.x + t.y; ai = z;
                t = __half22float2(af); ff += t.x + t.y; af = z;
                t = __half22float2(ag); fg += t.x + t.y; ag = z;
                t = __half22float2(ao); fo += t.x + t.y; ao = z;
            }
        }
        float iv = sigf(gxi + fi);
        float fv = sigf(gxf + ff);
        float gv = tanh_(gxg + fg);
        float ov = sigf(gxo + fo);
        c = fv * c + iv * gv;
        hval = ov * tanh_(c);
        __syncthreads();                         // all reads of h_{s-1} done
        hsh[seq * 128 + gb] = __float2half(hval);
        __syncthreads();                         // h_s visible
    }
    g_ctx[path * 256 + dir * 128 + gb] = hval;   // [hf | hb]
}

// ---------------- phase D: attention -----------------------------------------
// att1: per-path score = d2w . tanh([ctx,u] @ d1wT + d1b) + d2b
__global__ void __launch_bounds__(256) att1_kernel(const float* __restrict__ d1b,
                                                   const float* __restrict__ d2w,
                                                   const float* __restrict__ d2b) {
    __shared__ float cat[512];
    __shared__ float red[256];
    int p = blockIdx.x, tid = threadIdx.x;
    cat[tid]       = g_ctx[p * 256 + tid];
    cat[256 + tid] = g_u[tid];
    __syncthreads();
    float acc = d1b[tid];
#pragma unroll 8
    for (int k = 0; k < 512; k++) acc += cat[k] * g_d1wT[k * 256 + tid];
    red[tid] = tanh_(acc) * d2w[tid];
    __syncthreads();
    for (int s = 128; s > 0; s >>= 1) {
        if (tid < s) red[tid] += red[tid + s];
        __syncthreads();
    }
    if (tid == 0) g_score[p] = red[0] + d2b[0];
}

// att2: softmax over scores, o = sum(alpha*ctx), u = [u,o] @ d1wT + d1b
__global__ void __launch_bounds__(256) att2_kernel(const float* __restrict__ d1b) {
    __shared__ float al[128];
    __shared__ float red[128];
    __shared__ float cat[512];
    int tid = threadIdx.x;
    cat[tid] = g_u[tid];             // old u first
    if (tid < 128) red[tid] = g_score[tid];
    __syncthreads();
    for (int s = 64; s > 0; s >>= 1) {
        if (tid < s) red[tid] = fmaxf(red[tid], red[tid + s]);
        __syncthreads();
    }
    float m = red[0];
    __syncthreads();
    if (tid < 128) { float e = __expf(g_score[tid] - m); al[tid] = e; red[tid] = e; }
    __syncthreads();
    for (int s = 64; s > 0; s >>= 1) {
        if (tid < s) red[tid] += red[tid + s];
        __syncthreads();
    }
    float inv = __fdividef(1.f, red[0]);
    float o = 0.f;
#pragma unroll 8
    for (int p = 0; p < 128; p++) o += al[p] * g_ctx[p * 256 + tid];
    cat[256 + tid] = o * inv;
    __syncthreads();
    float acc = d1b[tid];
#pragma unroll 8
    for (int k = 0; k < 512; k++) acc += cat[k] * g_d1wT[k * 256 + tid];
    __syncthreads();
    g_u[tid] = acc;
}

__global__ void __launch_bounds__(256) final_kernel(const float* __restrict__ d2w,
                                                    const float* __restrict__ d2b,
                                                    float* __restrict__ out) {
    __shared__ float red[256];
    int tid = threadIdx.x;
    red[tid] = fmaxf(g_u[tid], 0.f) * d2w[tid];
    __syncthreads();
    for (int s = 128; s > 0; s >>= 1) {
        if (tid < s) red[tid] += red[tid + s];
        __syncthreads();
    }
    if (tid == 0) out[0] = __fdividef(1.f, 1.f + __expf(-(red[0] + d2b[0])));
}

// ---------------- launch ------------------------------------------------------
extern "C" void kernel_launch(void* const* d_in, const int* in_sizes, int n_in,
                              void* d_out, int out_size) {
    const int*   path   = (const int*)  d_in[0];
    const int*   query  = (const int*)  d_in[1];
    const float* embA   = (const float*)d_in[2];
    const float* embB   = (const float*)d_in[3];
    const float* conv_w = (const float*)d_in[4];
    const float* conv_b = (const float*)d_in[5];
    const float* wihf   = (const float*)d_in[6];
    const float* whhf   = (const float*)d_in[7];
    const float* bihf   = (const float*)d_in[8];
    const float* bhhf   = (const float*)d_in[9];
    const float* wihb   = (const float*)d_in[10];
    const float* whhb   = (const float*)d_in[11];
    const float* bihb   = (const float*)d_in[12];
    const float* bhhb   = (const float*)d_in[13];
    const float* d1w    = (const float*)d_in[14];
    const float* d1b    = (const float*)d_in[15];
    const float* d2w    = (const float*)d_in[16];
    const float* d2b    = (const float*)d_in[17];
    float* out = (float*)d_out;

    const int gemm_smem = 2 * 128 * 132 * 4;           // 135168
    const int lstm_smem = 512 * WROW * 2 + 1024;       // 140288
    cudaFuncSetAttribute(gemm_kernel, cudaFuncAttributeMaxDynamicSharedMemorySize, gemm_smem);
    cudaFuncSetAttribute(lstm_kernel, cudaFuncAttributeMaxDynamicSharedMemorySize, lstm_smem);

    prep_kernel<<<896, 256>>>(conv_w, d1w);
    init_u_kernel<<<1, 256>>>(query, embB);
    conv_kernel<<<dim3(16, 128), 128>>>(path, embA, conv_b);
    gemm_kernel<<<dim3(509, 8), 256, gemm_smem>>>(wihf, wihb, bihf, bhhf, bihb, bhhb);
    lstm_kernel<<<128, 256, lstm_smem>>>(whhf, whhb);
    for (int it = 0; it < 2; it++) {
        att1_kernel<<<128, 256>>>(d1b, d2w, d2b);
        att2_kernel<<<1, 256>>>(d1b);
    }
    final_kernel<<<1, 256>>>(d2w, d2b, out);
}

// round 3
// speedup vs baseline: 1.5090x; 1.5090x over previous
#include <cuda_runtime.h>
#include <cuda_fp16.h>
#include <math.h>

#define Pn 128
#define Ln 512
#define En 256
#define Fn 128
#define Tn 509

// ---------------- scratch (device globals; allocation is forbidden) ----------
__device__ float  g_xs [(size_t)Pn * Tn * Fn];     // conv output [p][t][f]
__device__ float  g_gx [(size_t)Pn * Tn * 1024];   // input gates [p*T][fwd512|bwd512]
__device__ float  g_ctx[Pn * En];                  // BiLSTM context [p][2H]
__device__ float2 g_cw2[128 * 3 * Fn];             // conv_w paired over e: [(e2*3+k)][f] -> (w[2e2], w[2e2+1])
__device__ float  g_d1wT[512 * 256];               // d1_w transposed [k][e]
__device__ float  g_score[Pn];
__device__ float  g_u[En];

// ---------------- helpers ----------------------------------------------------
__device__ __forceinline__ float sigf(float x) {
    return __fdividef(1.f, 1.f + __expf(-x));
}
__device__ __forceinline__ float tanh_(float x) {
    return __fdividef(2.f, 1.f + __expf(-2.f * x)) - 1.f;
}
union UH { unsigned int u; __half2 h; };
__device__ __forceinline__ __half2 as_h2(unsigned int x) { UH v; v.u = x; return v.h; }

// packed fp32x2 (Blackwell FFMA2 path — only reachable via PTX)
__device__ __forceinline__ unsigned long long pk2(float x, float y) {
    unsigned long long r;
    asm("mov.b64 %0, {%1,%2};" : "=l"(r) : "f"(x), "f"(y));
    return r;
}
__device__ __forceinline__ void fma2(unsigned long long& d, unsigned long long a, unsigned long long b) {
    asm("fma.rn.f32x2 %0, %1, %2, %0;" : "+l"(d) : "l"(a), "l"(b));
}
__device__ __forceinline__ float2 upk2(unsigned long long v) {
    float2 r;
    asm("mov.b64 {%0,%1}, %2;" : "=f"(r.x), "=f"(r.y) : "l"(v));
    return r;
}

// ---------------- prep: weight reshapes --------------------------------------
__global__ void prep_kernel(const float* __restrict__ conv_w,
                            const float* __restrict__ d1w) {
    int idx = blockIdx.x * blockDim.x + threadIdx.x;
    if (idx < 128 * 3 * Fn) {                  // 49152: cw2[(e2*3+k)*128+f]
        int f = idx & 127, ek = idx >> 7;
        int e2 = ek / 3, k = ek - e2 * 3;
        float a = conv_w[(size_t)f * 768 + (2 * e2) * 3 + k];
        float b = conv_w[(size_t)f * 768 + (2 * e2 + 1) * 3 + k];
        g_cw2[idx] = make_float2(a, b);
    } else {
        int j = idx - 128 * 3 * Fn;
        if (j < 512 * 256) {                   // 131072: d1wT[k*256+e]
            int e = j & 255, k = j >> 8;
            g_d1wT[j] = d1w[(size_t)e * 512 + k];
        }
    }
}

__global__ void init_u_kernel(const int* __restrict__ q,
                              const float* __restrict__ embB) {
    int t = threadIdx.x;
    g_u[t] = embB[(size_t)q[0] * En + t];
}

// ---------------- phase A: embed + conv + relu + maxpool ----------------------
// grid (16 tiles, 128 paths), 128 threads (thread = filter f)
// f32x2 accumulation over (even e, odd e) pairs.
__global__ void __launch_bounds__(128) conv_kernel(const int* __restrict__ path,
                                                   const float* __restrict__ embA,
                                                   const float* __restrict__ conv_b) {
    __shared__ __align__(16) float esh[35 * En];   // 35 token embeddings (35 KB)
    int p  = blockIdx.y;
    int l0 = blockIdx.x * 32;
    int f  = threadIdx.x;

    for (int i = 0; i < 35; i++) {
        int lt = l0 + i;
        float2 v = make_float2(0.f, 0.f);
        if (lt < Ln) {
            int tok = path[p * Ln + lt];
            v = *(const float2*)(embA + (size_t)tok * En + f * 2);
        }
        *(float2*)(esh + i * En + f * 2) = v;
    }
    __syncthreads();

    unsigned long long acc2[33];
#pragma unroll
    for (int l = 0; l < 33; l++) acc2[l] = 0ull;

    for (int e2 = 0; e2 < 128; e2++) {
        float2 w0f = g_cw2[(e2 * 3 + 0) * Fn + f];
        float2 w1f = g_cw2[(e2 * 3 + 1) * Fn + f];
        float2 w2f = g_cw2[(e2 * 3 + 2) * Fn + f];
        unsigned long long w0 = pk2(w0f.x, w0f.y);
        unsigned long long w1 = pk2(w1f.x, w1f.y);
        unsigned long long w2 = pk2(w2f.x, w2f.y);
        const float* eb = esh + 2 * e2;
        unsigned long long p0 = *(const unsigned long long*)(eb);
        unsigned long long p1 = *(const unsigned long long*)(eb + En);
#pragma unroll
        for (int l = 0; l < 33; l++) {
            unsigned long long pz = *(const unsigned long long*)(eb + (l + 2) * En);
            fma2(acc2[l], w0, p0);
            fma2(acc2[l], w1, p1);
            fma2(acc2[l], w2, pz);
            p0 = p1; p1 = pz;
        }
    }

    float acc[33];
#pragma unroll
    for (int l = 0; l < 33; l++) {
        float2 r = upk2(acc2[l]);
        acc[l] = r.x + r.y;
    }

    float b = conv_b[f];
#pragma unroll
    for (int l = 0; l < 32; l++) {
        int t = l0 + l;
        if (t < Tn) {
            float m = fmaxf(acc[l], acc[l + 1]);             // maxpool(2, stride 1)
            g_xs[((size_t)p * Tn + t) * Fn + f] = fmaxf(m + b, 0.f);
        }
    }
}

// ---------------- phase B: input-gate GEMM (f32x2) ----------------------------
// gx[row][col] = xs[row][:] . W[col][:] + bias[col];  rows = 65152, cols = 1024
__global__ void __launch_bounds__(256) gemm_kernel(
        const float* __restrict__ wihf, const float* __restrict__ wihb,
        const float* __restrict__ bihf, const float* __restrict__ bhhf,
        const float* __restrict__ bihb, const float* __restrict__ bhhb) {
    extern __shared__ float smf[];
    float* As = smf;                 // [k=128][r=132 padded]
    float* Bs = smf + 128 * 132;     // [k=128][c=132 padded]
    __shared__ float bias_s[128];

    int row0 = blockIdx.x * 128;
    int by   = blockIdx.y;
    int tid  = threadIdx.x;

    const float* Bp = (by < 4) ? (wihf + (size_t)by * 128 * 128)
                               : (wihb + (size_t)(by - 4) * 128 * 128);
    if (tid < 128) {
        bias_s[tid] = (by < 4) ? (bihf[by * 128 + tid] + bhhf[by * 128 + tid])
                               : (bihb[(by - 4) * 128 + tid] + bhhb[(by - 4) * 128 + tid]);
    }
    for (int idx = tid; idx < 16384; idx += 256) {
        int r = idx >> 7, k = idx & 127;
        As[k * 132 + r] = g_xs[(size_t)(row0 + r) * 128 + k];
        Bs[k * 132 + r] = Bp[idx];
    }
    __syncthreads();

    int tx = tid & 15, ty = tid >> 4;
    unsigned long long acc2[8][4];
#pragma unroll
    for (int i = 0; i < 8; i++)
#pragma unroll
        for (int j = 0; j < 4; j++) acc2[i][j] = 0ull;

#pragma unroll 4
    for (int k = 0; k < 128; k++) {
        float4 a0 = *(const float4*)(As + k * 132 + ty * 8);
        float4 a1 = *(const float4*)(As + k * 132 + ty * 8 + 4);
        ulonglong2 bq0 = *(const ulonglong2*)(Bs + k * 132 + tx * 8);
        ulonglong2 bq1 = *(const ulonglong2*)(Bs + k * 132 + tx * 8 + 4);
        unsigned long long bv[4] = {bq0.x, bq0.y, bq1.x, bq1.y};
        float av[8] = {a0.x, a0.y, a0.z, a0.w, a1.x, a1.y, a1.z, a1.w};
#pragma unroll
        for (int i = 0; i < 8; i++) {
            unsigned long long ap = pk2(av[i], av[i]);
#pragma unroll
            for (int j = 0; j < 4; j++) fma2(acc2[i][j], ap, bv[j]);
        }
    }

#pragma unroll
    for (int i = 0; i < 8; i++) {
        float* op = g_gx + (size_t)(row0 + ty * 8 + i) * 1024 + by * 128 + tx * 8;
        const float* bb = bias_s + tx * 8;
#pragma unroll
        for (int j = 0; j < 4; j++) {
            float2 r = upk2(acc2[i][j]);
            op[2 * j]     = r.x + bb[2 * j];
            op[2 * j + 1] = r.y + bb[2 * j + 1];
        }
    }
}

// ---------------- phase C: LSTM recurrence (register-resident weights) --------
// 128 CTAs: bid = (pair<<1)|dir.  256 threads: tid = gb*2 + kh.
// Thread holds W_hh rows {gb, gb+128, gb+256, gb+384}, k in [kh*64, kh*64+64)
// as 128 half2 REGISTERS, and accumulates partial gate sums for BOTH sequences
// of the pair each step (weights read once, not twice). Partner partials are
// combined with one shfl.bfly per gate. Thread owns c/h of sequence seq==kh.
__global__ void __launch_bounds__(256, 1) lstm_kernel(const float* __restrict__ whhf,
                                                      const float* __restrict__ whhb) {
    __shared__ __align__(16) __half hsh[2][2][136];   // [buf][seq][h]

    int bid  = blockIdx.x;
    int dir  = bid & 1;
    int pair = bid >> 1;
    int tid  = threadIdx.x;
    int gb   = tid >> 1;
    int kh   = tid & 1;

    const float* whh = dir ? whhb : whhf;

    __half2 wreg[4][32];
#pragma unroll
    for (int g = 0; g < 4; g++) {
        const float2* wp = (const float2*)(whh + (size_t)(gb + g * 128) * 128 + kh * 64);
#pragma unroll
        for (int j = 0; j < 32; j++) wreg[g][j] = __float22half2_rn(wp[j]);
    }

    // zero both h buffers
    if (tid < 136) {
        hsh[0][0][tid] = __float2half(0.f); hsh[0][1][tid] = __float2half(0.f);
        hsh[1][0][tid] = __float2half(0.f); hsh[1][1][tid] = __float2half(0.f);
    }
    __syncthreads();

    int mypath = pair * 2 + kh;
    const float* gxbase = g_gx + (size_t)mypath * Tn * 1024 + dir * 512 + gb;

    float c = 0.f, hval = 0.f;
    const __half2 z = __float2half2_rn(0.f);

    int tt0 = dir ? (Tn - 1) : 0;
    const float* gp0 = gxbase + (size_t)tt0 * 1024;
    float gxi = gp0[0], gxf = gp0[128], gxg = gp0[256], gxo = gp0[384];

    for (int s = 0; s < Tn; s++) {
        // prefetch next step's gx (clamped; overlaps with accumulation below)
        int sn = (s + 1 < Tn) ? s + 1 : s;
        int ttn = dir ? (Tn - 1 - sn) : sn;
        const float* gn = gxbase + (size_t)ttn * 1024;
        float ni = gn[0], nf = gn[128], ng = gn[256], no = gn[384];

        int cb = s & 1;
        float sA[4], sB[4];
        // ---- sequence 0 ----
        {
            const uint4* h4 = (const uint4*)(&hsh[cb][0][kh * 64]);
            __half2 a0 = z, a1 = z, a2 = z, a3 = z;
            float f0 = 0.f, f1 = 0.f, f2 = 0.f, f3 = 0.f;
#pragma unroll
            for (int q = 0; q < 8; q++) {
                uint4 hv = h4[q];
                __half2 h0 = as_h2(hv.x), h1 = as_h2(hv.y), h2v = as_h2(hv.z), h3 = as_h2(hv.w);
                a0 = __hfma2(wreg[0][q*4+0], h0, a0); a0 = __hfma2(wreg[0][q*4+1], h1, a0);
                a0 = __hfma2(wreg[0][q*4+2], h2v, a0); a0 = __hfma2(wreg[0][q*4+3], h3, a0);
                a1 = __hfma2(wreg[1][q*4+0], h0, a1); a1 = __hfma2(wreg[1][q*4+1], h1, a1);
                a1 = __hfma2(wreg[1][q*4+2], h2v, a1); a1 = __hfma2(wreg[1][q*4+3], h3, a1);
                a2 = __hfma2(wreg[2][q*4+0], h0, a2); a2 = __hfma2(wreg[2][q*4+1], h1, a2);
                a2 = __hfma2(wreg[2][q*4+2], h2v, a2); a2 = __hfma2(wreg[2][q*4+3], h3, a2);
                a3 = __hfma2(wreg[3][q*4+0], h0, a3); a3 = __hfma2(wreg[3][q*4+1], h1, a3);
                a3 = __hfma2(wreg[3][q*4+2], h2v, a3); a3 = __hfma2(wreg[3][q*4+3], h3, a3);
                if (q == 3 || q == 7) {
                    float2 t;
                    t = __half22float2(a0); f0 += t.x + t.y; a0 = z;
                    t = __half22float2(a1); f1 += t.x + t.y; a1 = z;
                    t = __half22float2(a2); f2 += t.x + t.y; a2 = z;
                    t = __half22float2(a3); f3 += t.x + t.y; a3 = z;
                }
            }
            sA[0] = f0; sA[1] = f1; sA[2] = f2; sA[3] = f3;
        }
        // ---- sequence 1 ----
        {
            const uint4* h4 = (const uint4*)(&hsh[cb][1][kh * 64]);
            __half2 a0 = z, a1 = z, a2 = z, a3 = z;
            float f0 = 0.f, f1 = 0.f, f2 = 0.f, f3 = 0.f;
#pragma unroll
            for (int q = 0; q < 8; q++) {
                uint4 hv = h4[q];
                __half2 h0 = as_h2(hv.x), h1 = as_h2(hv.y), h2v = as_h2(hv.z), h3 = as_h2(hv.w);
                a0 = __hfma2(wreg[0][q*4+0], h0, a0); a0 = __hfma2(wreg[0][q*4+1], h1, a0);
                a0 = __hfma2(wreg[0][q*4+2], h2v, a0); a0 = __hfma2(wreg[0][q*4+3], h3, a0);
                a1 = __hfma2(wreg[1][q*4+0], h0, a1); a1 = __hfma2(wreg[1][q*4+1], h1, a1);
                a1 = __hfma2(wreg[1][q*4+2], h2v, a1); a1 = __hfma2(wreg[1][q*4+3], h3, a1);
                a2 = __hfma2(wreg[2][q*4+0], h0, a2); a2 = __hfma2(wreg[2][q*4+1], h1, a2);
                a2 = __hfma2(wreg[2][q*4+2], h2v, a2); a2 = __hfma2(wreg[2][q*4+3], h3, a2);
                a3 = __hfma2(wreg[3][q*4+0], h0, a3); a3 = __hfma2(wreg[3][q*4+1], h1, a3);
                a3 = __hfma2(wreg[3][q*4+2], h2v, a3); a3 = __hfma2(wreg[3][q*4+3], h3, a3);
                if (q == 3 || q == 7) {
                    float2 t;
                    t = __half22float2(a0); f0 += t.x + t.y; a0 = z;
                    t = __half22float2(a1); f1 += t.x + t.y; a1 = z;
                    t = __half22float2(a2); f2 += t.x + t.y; a2 = z;
                    t = __half22float2(a3); f3 += t.x + t.y; a3 = z;
                }
            }
            sB[0] = f0; sB[1] = f1; sB[2] = f2; sB[3] = f3;
        }

        // combine with partner: full own-seq sum = own partial + partner's same-seq partial
        float own[4], full[4];
#pragma unroll
        for (int g = 0; g < 4; g++) {
            own[g]       = kh ? sB[g] : sA[g];
            float other  = kh ? sA[g] : sB[g];   // partner needs this one
            full[g] = own[g] + __shfl_xor_sync(0xffffffffu, other, 1);
        }

        float iv = sigf (gxi + full[0]);
        float fv = sigf (gxf + full[1]);
        float gv = tanh_(gxg + full[2]);
        float ov = sigf (gxo + full[3]);
        c = fv * c + iv * gv;
        hval = ov * tanh_(c);

        hsh[cb ^ 1][kh][gb] = __float2half(hval);
        __syncthreads();

        gxi = ni; gxf = nf; gxg = ng; gxo = no;
    }
    g_ctx[mypath * 256 + dir * 128 + gb] = hval;
}

// ---------------- phase D: attention -----------------------------------------
__global__ void __launch_bounds__(256) att1_kernel(const float* __restrict__ d1b,
                                                   const float* __restrict__ d2w,
                                                   const float* __restrict__ d2b) {
    __shared__ float cat[512];
    __shared__ float red[256];
    int p = blockIdx.x, tid = threadIdx.x;
    cat[tid]       = g_ctx[p * 256 + tid];
    cat[256 + tid] = g_u[tid];
    __syncthreads();
    float acc = d1b[tid];
#pragma unroll 8
    for (int k = 0; k < 512; k++) acc += cat[k] * g_d1wT[k * 256 + tid];
    red[tid] = tanh_(acc) * d2w[tid];
    __syncthreads();
    for (int s = 128; s > 0; s >>= 1) {
        if (tid < s) red[tid] += red[tid + s];
        __syncthreads();
    }
    if (tid == 0) g_score[p] = red[0] + d2b[0];
}

__global__ void __launch_bounds__(256) att2_kernel(const float* __restrict__ d1b) {
    __shared__ float al[128];
    __shared__ float red[128];
    __shared__ float cat[512];
    int tid = threadIdx.x;
    cat[tid] = g_u[tid];
    if (tid < 128) red[tid] = g_score[tid];
    __syncthreads();
    for (int s = 64; s > 0; s >>= 1) {
        if (tid < s) red[tid] = fmaxf(red[tid], red[tid + s]);
        __syncthreads();
    }
    float m = red[0];
    __syncthreads();
    if (tid < 128) { float e = __expf(g_score[tid] - m); al[tid] = e; red[tid] = e; }
    __syncthreads();
    for (int s = 64; s > 0; s >>= 1) {
        if (tid < s) red[tid] += red[tid + s];
        __syncthreads();
    }
    float inv = __fdividef(1.f, red[0]);
    float o = 0.f;
#pragma unroll 8
    for (int p = 0; p < 128; p++) o += al[p] * g_ctx[p * 256 + tid];
    cat[256 + tid] = o * inv;
    __syncthreads();
    float acc = d1b[tid];
#pragma unroll 8
    for (int k = 0; k < 512; k++) acc += cat[k] * g_d1wT[k * 256 + tid];
    __syncthreads();
    g_u[tid] = acc;
}

__global__ void __launch_bounds__(256) final_kernel(const float* __restrict__ d2w,
                                                    const float* __restrict__ d2b,
                                                    float* __restrict__ out) {
    __shared__ float red[256];
    int tid = threadIdx.x;
    red[tid] = fmaxf(g_u[tid], 0.f) * d2w[tid];
    __syncthreads();
    for (int s = 128; s > 0; s >>= 1) {
        if (tid < s) red[tid] += red[tid + s];
        __syncthreads();
    }
    if (tid == 0) out[0] = __fdividef(1.f, 1.f + __expf(-(red[0] + d2b[0])));
}

// ---------------- launch ------------------------------------------------------
extern "C" void kernel_launch(void* const* d_in, const int* in_sizes, int n_in,
                              void* d_out, int out_size) {
    const int*   path   = (const int*)  d_in[0];
    const int*   query  = (const int*)  d_in[1];
    const float* embA   = (const float*)d_in[2];
    const float* embB   = (const float*)d_in[3];
    const float* conv_w = (const float*)d_in[4];
    const float* conv_b = (const float*)d_in[5];
    const float* wihf   = (const float*)d_in[6];
    const float* whhf   = (const float*)d_in[7];
    const float* bihf   = (const float*)d_in[8];
    const float* bhhf   = (const float*)d_in[9];
    const float* wihb   = (const float*)d_in[10];
    const float* whhb   = (const float*)d_in[11];
    const float* bihb   = (const float*)d_in[12];
    const float* bhhb   = (const float*)d_in[13];
    const float* d1w    = (const float*)d_in[14];
    const float* d1b    = (const float*)d_in[15];
    const float* d2w    = (const float*)d_in[16];
    const float* d2b    = (const float*)d_in[17];
    float* out = (float*)d_out;

    const int gemm_smem = 2 * 128 * 132 * 4;           // 135168
    cudaFuncSetAttribute(gemm_kernel, cudaFuncAttributeMaxDynamicSharedMemorySize, gemm_smem);

    prep_kernel<<<704, 256>>>(conv_w, d1w);
    init_u_kernel<<<1, 256>>>(query, embB);
    conv_kernel<<<dim3(16, 128), 128>>>(path, embA, conv_b);
    gemm_kernel<<<dim3(509, 8), 256, gemm_smem>>>(wihf, wihb, bihf, bhhf, bihb, bhhb);
    lstm_kernel<<<128, 256>>>(whhf, whhb);
    for (int it = 0; it < 2; it++) {
        att1_kernel<<<128, 256>>>(d1b, d2w, d2b);
        att2_kernel<<<1, 256>>>(d1b);
    }
    final_kernel<<<1, 256>>>(d2w, d2b, out);
}

// round 4
// speedup vs baseline: 2.3222x; 1.5389x over previous
#include <cuda_runtime.h>
#include <cuda_fp16.h>
#include <math.h>

#define Pn 128
#define Ln 512
#define En 256
#define Fn 128
#define Tn 509

// ---------------- scratch (device globals; allocation is forbidden) ----------
__device__ __half  g_xsh[(size_t)Pn * Tn * Fn];    // conv output fp16 [p][t][f]
__device__ float   g_gx [(size_t)Pn * Tn * 1024];  // input gates [p*T][fwd512|bwd512]
__device__ float   g_ctx[Pn * En];                 // BiLSTM context [p][2H]
__device__ float2  g_cw2[128 * 3 * Fn];            // conv_w paired over e
__device__ float   g_d1wT[512 * 256];              // d1_w transposed [k][e]
__device__ __half  g_wh [1024 * 128];              // W_ih fp16 [n(fwd512|bwd512)][k]
__device__ float   g_bias[1024];                   // combined b_ih + b_hh
__device__ float   g_score[Pn];
__device__ float   g_u[En];

// ---------------- helpers ----------------------------------------------------
__device__ __forceinline__ float sigf(float x) {
    return __fdividef(1.f, 1.f + __expf(-x));
}
__device__ __forceinline__ float tanh_(float x) {
    return __fdividef(2.f, 1.f + __expf(-2.f * x)) - 1.f;
}
union UH { unsigned int u; __half2 h; };
__device__ __forceinline__ __half2 as_h2(unsigned int x) { UH v; v.u = x; return v.h; }

// packed fp32x2 (conv path)
__device__ __forceinline__ unsigned long long pk2(float x, float y) {
    unsigned long long r;
    asm("mov.b64 %0, {%1,%2};" : "=l"(r) : "f"(x), "f"(y));
    return r;
}
__device__ __forceinline__ void fma2(unsigned long long& d, unsigned long long a, unsigned long long b) {
    asm("fma.rn.f32x2 %0, %1, %2, %0;" : "+l"(d) : "l"(a), "l"(b));
}
__device__ __forceinline__ float2 upk2(unsigned long long v) {
    float2 r;
    asm("mov.b64 {%0,%1}, %2;" : "=f"(r.x), "=f"(r.y) : "l"(v));
    return r;
}

__device__ __forceinline__ void ldm_x4(unsigned& r0, unsigned& r1, unsigned& r2, unsigned& r3,
                                       unsigned addr) {
    asm volatile("ldmatrix.sync.aligned.m8n8.x4.shared.b16 {%0,%1,%2,%3}, [%4];"
                 : "=r"(r0), "=r"(r1), "=r"(r2), "=r"(r3) : "r"(addr));
}
__device__ __forceinline__ void mma16816(float* c, const unsigned* a, unsigned b0, unsigned b1) {
    asm volatile("mma.sync.aligned.m16n8k16.row.col.f32.f16.f16.f32 "
                 "{%0,%1,%2,%3}, {%4,%5,%6,%7}, {%8,%9}, {%0,%1,%2,%3};"
                 : "+f"(c[0]), "+f"(c[1]), "+f"(c[2]), "+f"(c[3])
                 : "r"(a[0]), "r"(a[1]), "r"(a[2]), "r"(a[3]), "r"(b0), "r"(b1));
}

// ---------------- prep: weight reshapes --------------------------------------
__global__ void prep_kernel(const float* __restrict__ conv_w,
                            const float* __restrict__ d1w,
                            const float* __restrict__ wihf, const float* __restrict__ wihb,
                            const float* __restrict__ bihf, const float* __restrict__ bhhf,
                            const float* __restrict__ bihb, const float* __restrict__ bhhb) {
    int idx = blockIdx.x * blockDim.x + threadIdx.x;
    if (idx < 49152) {                        // cw2[(e2*3+k)*128+f]
        int f = idx & 127, ek = idx >> 7;
        int e2 = ek / 3, k = ek - e2 * 3;
        float a = conv_w[(size_t)f * 768 + (2 * e2) * 3 + k];
        float b = conv_w[(size_t)f * 768 + (2 * e2 + 1) * 3 + k];
        g_cw2[idx] = make_float2(a, b);
    } else if (idx < 49152 + 131072) {        // d1wT[k*256+e]
        int j = idx - 49152;
        int e = j & 255, k = j >> 8;
        g_d1wT[j] = d1w[(size_t)e * 512 + k];
    } else if (idx < 180224 + 131072) {       // g_wh[n][k] fp16
        int j = idx - 180224;
        int k = j & 127, n = j >> 7;
        float w = (n < 512) ? wihf[(size_t)n * 128 + k] : wihb[(size_t)(n - 512) * 128 + k];
        g_wh[j] = __float2half(w);
    } else if (idx < 311296 + 1024) {         // g_bias[n]
        int n = idx - 311296;
        g_bias[n] = (n < 512) ? (bihf[n] + bhhf[n]) : (bihb[n - 512] + bhhb[n - 512]);
    }
}

__global__ void init_u_kernel(const int* __restrict__ q,
                              const float* __restrict__ embB) {
    int t = threadIdx.x;
    g_u[t] = embB[(size_t)q[0] * En + t];
}

// ---------------- phase A: embed + conv + relu + maxpool ----------------------
__global__ void __launch_bounds__(128) conv_kernel(const int* __restrict__ path,
                                                   const float* __restrict__ embA,
                                                   const float* __restrict__ conv_b) {
    __shared__ __align__(16) float esh[35 * En];
    int p  = blockIdx.y;
    int l0 = blockIdx.x * 32;
    int f  = threadIdx.x;

    for (int i = 0; i < 35; i++) {
        int lt = l0 + i;
        float2 v = make_float2(0.f, 0.f);
        if (lt < Ln) {
            int tok = path[p * Ln + lt];
            v = *(const float2*)(embA + (size_t)tok * En + f * 2);
        }
        *(float2*)(esh + i * En + f * 2) = v;
    }
    __syncthreads();

    unsigned long long acc2[33];
#pragma unroll
    for (int l = 0; l < 33; l++) acc2[l] = 0ull;

    for (int e2 = 0; e2 < 128; e2++) {
        float2 w0f = g_cw2[(e2 * 3 + 0) * Fn + f];
        float2 w1f = g_cw2[(e2 * 3 + 1) * Fn + f];
        float2 w2f = g_cw2[(e2 * 3 + 2) * Fn + f];
        unsigned long long w0 = pk2(w0f.x, w0f.y);
        unsigned long long w1 = pk2(w1f.x, w1f.y);
        unsigned long long w2 = pk2(w2f.x, w2f.y);
        const float* eb = esh + 2 * e2;
        unsigned long long p0 = *(const unsigned long long*)(eb);
        unsigned long long p1 = *(const unsigned long long*)(eb + En);
#pragma unroll
        for (int l = 0; l < 33; l++) {
            unsigned long long pz = *(const unsigned long long*)(eb + (l + 2) * En);
            fma2(acc2[l], w0, p0);
            fma2(acc2[l], w1, p1);
            fma2(acc2[l], w2, pz);
            p0 = p1; p1 = pz;
        }
    }

    float acc[33];
#pragma unroll
    for (int l = 0; l < 33; l++) {
        float2 r = upk2(acc2[l]);
        acc[l] = r.x + r.y;
    }

    float b = conv_b[f];
#pragma unroll
    for (int l = 0; l < 32; l++) {
        int t = l0 + l;
        if (t < Tn) {
            float m = fmaxf(acc[l], acc[l + 1]);
            g_xsh[((size_t)p * Tn + t) * Fn + f] = __float2half(fmaxf(m + b, 0.f));
        }
    }
}

// ---------------- phase B: input-gate GEMM (tensor cores) ---------------------
// gx[row][n] = xs[row][:] . W[n][:] + bias[n];  rows = 65152, n = 1024
// CTA tile 128x128, K=128 one shot; 8 warps, warp tile 64x32; mma.m16n8k16.
#define SROW 136   // halves per smem row (272 B: ldmatrix conflict-free)
__global__ void __launch_bounds__(256) gemm_kernel() {
    extern __shared__ __half smh[];
    __half* As = smh;                 // [128 m][SROW]
    __half* Bs = smh + 128 * SROW;    // [128 n][SROW]
    __shared__ float bias_s[128];

    int row0 = blockIdx.x * 128;
    int col0 = blockIdx.y * 128;
    int tid  = threadIdx.x;
    int wid  = tid >> 5, lane = tid & 31;
    int m0 = (wid >> 2) * 64;         // warp m offset in tile
    int n0 = (wid & 3) * 32;          // warp n offset in tile

    if (tid < 128) bias_s[tid] = g_bias[col0 + tid];

    // load A,B tiles: 2048 uint4 each
    {
        const uint4* asrc = (const uint4*)(g_xsh + (size_t)row0 * 128);
        const uint4* bsrc = (const uint4*)(g_wh + (size_t)col0 * 128);
        for (int idx = tid; idx < 2048; idx += 256) {
            int r = idx >> 4, c = idx & 15;
            *(uint4*)(As + r * SROW + c * 8) = asrc[r * 16 + c];
            *(uint4*)(Bs + r * SROW + c * 8) = bsrc[r * 16 + c];
        }
    }
    __syncthreads();

    // ldmatrix base addresses (bytes)
    unsigned sbase = (unsigned)__cvta_generic_to_shared(smh);
    unsigned aAddr[4], bAddr[2];
#pragma unroll
    for (int mi = 0; mi < 4; mi++) {
        int r = m0 + mi * 16 + (lane & 15);
        int ch = (lane >> 4) * 8;
        aAddr[mi] = sbase + (r * SROW + ch) * 2;
    }
#pragma unroll
    for (int bj = 0; bj < 2; bj++) {
        int r = n0 + bj * 16 + (lane & 7) + ((lane >> 4) << 3);
        int ch = ((lane >> 3) & 1) * 8;
        bAddr[bj] = sbase + (128 * SROW + r * SROW + ch) * 2;
    }

    float acc[4][4][4];
#pragma unroll
    for (int mi = 0; mi < 4; mi++)
#pragma unroll
        for (int nj = 0; nj < 4; nj++)
#pragma unroll
            for (int q = 0; q < 4; q++) acc[mi][nj][q] = 0.f;

#pragma unroll
    for (int ks = 0; ks < 8; ks++) {
        unsigned a[4][4], b[2][4];
#pragma unroll
        for (int mi = 0; mi < 4; mi++)
            ldm_x4(a[mi][0], a[mi][1], a[mi][2], a[mi][3], aAddr[mi] + ks * 32);
#pragma unroll
        for (int bj = 0; bj < 2; bj++)
            ldm_x4(b[bj][0], b[bj][1], b[bj][2], b[bj][3], bAddr[bj] + ks * 32);
#pragma unroll
        for (int mi = 0; mi < 4; mi++)
#pragma unroll
            for (int nj = 0; nj < 4; nj++)
                mma16816(acc[mi][nj], a[mi], b[nj >> 1][(nj & 1) * 2], b[nj >> 1][(nj & 1) * 2 + 1]);
    }

    // epilogue: add bias, store float2
    int qr = lane >> 2, qc = (lane & 3) * 2;
#pragma unroll
    for (int mi = 0; mi < 4; mi++) {
#pragma unroll
        for (int nj = 0; nj < 4; nj++) {
            int cc = n0 + nj * 8 + qc;
            float bx = bias_s[cc], by = bias_s[cc + 1];
            size_t base = (size_t)(row0 + m0 + mi * 16 + qr) * 1024 + col0 + cc;
            *(float2*)(g_gx + base) = make_float2(acc[mi][nj][0] + bx, acc[mi][nj][1] + by);
            size_t base2 = base + (size_t)8 * 1024;
            *(float2*)(g_gx + base2) = make_float2(acc[mi][nj][2] + bx, acc[mi][nj][3] + by);
        }
    }
}

// ---------------- phase C: LSTM recurrence (register-resident weights) --------
__global__ void __launch_bounds__(256, 1) lstm_kernel(const float* __restrict__ whhf,
                                                      const float* __restrict__ whhb) {
    __shared__ __align__(16) __half hsh[2][2][136];   // [buf][seq][h]

    int bid  = blockIdx.x;
    int dir  = bid & 1;
    int pair = bid >> 1;
    int tid  = threadIdx.x;
    int gb   = tid >> 1;
    int kh   = tid & 1;

    const float* whh = dir ? whhb : whhf;

    __half2 wreg[4][32];
#pragma unroll
    for (int g = 0; g < 4; g++) {
        const float2* wp = (const float2*)(whh + (size_t)(gb + g * 128) * 128 + kh * 64);
#pragma unroll
        for (int j = 0; j < 32; j++) wreg[g][j] = __float22half2_rn(wp[j]);
    }

    if (tid < 136) {
        hsh[0][0][tid] = __float2half(0.f); hsh[0][1][tid] = __float2half(0.f);
        hsh[1][0][tid] = __float2half(0.f); hsh[1][1][tid] = __float2half(0.f);
    }
    __syncthreads();

    int mypath = pair * 2 + kh;
    const float* gxbase = g_gx + (size_t)mypath * Tn * 1024 + dir * 512 + gb;

    float c = 0.f, hval = 0.f;
    const __half2 z = __float2half2_rn(0.f);

    int tt0 = dir ? (Tn - 1) : 0;
    const float* gp0 = gxbase + (size_t)tt0 * 1024;
    float gxi = gp0[0], gxf = gp0[128], gxg = gp0[256], gxo = gp0[384];

    for (int s = 0; s < Tn; s++) {
        int sn = (s + 1 < Tn) ? s + 1 : s;
        int ttn = dir ? (Tn - 1 - sn) : sn;
        const float* gn = gxbase + (size_t)ttn * 1024;
        float ni = gn[0], nf = gn[128], ng = gn[256], no = gn[384];

        int cb = s & 1;
        float sA[4], sB[4];
        {
            const uint4* h4 = (const uint4*)(&hsh[cb][0][kh * 64]);
            __half2 a0 = z, a1 = z, a2 = z, a3 = z;
            float f0 = 0.f, f1 = 0.f, f2 = 0.f, f3 = 0.f;
#pragma unroll
            for (int q = 0; q < 8; q++) {
                uint4 hv = h4[q];
                __half2 h0 = as_h2(hv.x), h1 = as_h2(hv.y), h2v = as_h2(hv.z), h3 = as_h2(hv.w);
                a0 = __hfma2(wreg[0][q*4+0], h0, a0); a0 = __hfma2(wreg[0][q*4+1], h1, a0);
                a0 = __hfma2(wreg[0][q*4+2], h2v, a0); a0 = __hfma2(wreg[0][q*4+3], h3, a0);
                a1 = __hfma2(wreg[1][q*4+0], h0, a1); a1 = __hfma2(wreg[1][q*4+1], h1, a1);
                a1 = __hfma2(wreg[1][q*4+2], h2v, a1); a1 = __hfma2(wreg[1][q*4+3], h3, a1);
                a2 = __hfma2(wreg[2][q*4+0], h0, a2); a2 = __hfma2(wreg[2][q*4+1], h1, a2);
                a2 = __hfma2(wreg[2][q*4+2], h2v, a2); a2 = __hfma2(wreg[2][q*4+3], h3, a2);
                a3 = __hfma2(wreg[3][q*4+0], h0, a3); a3 = __hfma2(wreg[3][q*4+1], h1, a3);
                a3 = __hfma2(wreg[3][q*4+2], h2v, a3); a3 = __hfma2(wreg[3][q*4+3], h3, a3);
                if (q == 3 || q == 7) {
                    float2 t;
                    t = __half22float2(a0); f0 += t.x + t.y; a0 = z;
                    t = __half22float2(a1); f1 += t.x + t.y; a1 = z;
                    t = __half22float2(a2); f2 += t.x + t.y; a2 = z;
                    t = __half22float2(a3); f3 += t.x + t.y; a3 = z;
                }
            }
            sA[0] = f0; sA[1] = f1; sA[2] = f2; sA[3] = f3;
        }
        {
            const uint4* h4 = (const uint4*)(&hsh[cb][1][kh * 64]);
            __half2 a0 = z, a1 = z, a2 = z, a3 = z;
            float f0 = 0.f, f1 = 0.f, f2 = 0.f, f3 = 0.f;
#pragma unroll
            for (int q = 0; q < 8; q++) {
                uint4 hv = h4[q];
                __half2 h0 = as_h2(hv.x), h1 = as_h2(hv.y), h2v = as_h2(hv.z), h3 = as_h2(hv.w);
                a0 = __hfma2(wreg[0][q*4+0], h0, a0); a0 = __hfma2(wreg[0][q*4+1], h1, a0);
                a0 = __hfma2(wreg[0][q*4+2], h2v, a0); a0 = __hfma2(wreg[0][q*4+3], h3, a0);
                a1 = __hfma2(wreg[1][q*4+0], h0, a1); a1 = __hfma2(wreg[1][q*4+1], h1, a1);
                a1 = __hfma2(wreg[1][q*4+2], h2v, a1); a1 = __hfma2(wreg[1][q*4+3], h3, a1);
                a2 = __hfma2(wreg[2][q*4+0], h0, a2); a2 = __hfma2(wreg[2][q*4+1], h1, a2);
                a2 = __hfma2(wreg[2][q*4+2], h2v, a2); a2 = __hfma2(wreg[2][q*4+3], h3, a2);
                a3 = __hfma2(wreg[3][q*4+0], h0, a3); a3 = __hfma2(wreg[3][q*4+1], h1, a3);
                a3 = __hfma2(wreg[3][q*4+2], h2v, a3); a3 = __hfma2(wreg[3][q*4+3], h3, a3);
                if (q == 3 || q == 7) {
                    float2 t;
                    t = __half22float2(a0); f0 += t.x + t.y; a0 = z;
                    t = __half22float2(a1); f1 += t.x + t.y; a1 = z;
                    t = __half22float2(a2); f2 += t.x + t.y; a2 = z;
                    t = __half22float2(a3); f3 += t.x + t.y; a3 = z;
                }
            }
            sB[0] = f0; sB[1] = f1; sB[2] = f2; sB[3] = f3;
        }

        float full[4];
#pragma unroll
        for (int g = 0; g < 4; g++) {
            float own   = kh ? sB[g] : sA[g];
            float other = kh ? sA[g] : sB[g];
            full[g] = own + __shfl_xor_sync(0xffffffffu, other, 1);
        }

        float iv = sigf (gxi + full[0]);
        float fv = sigf (gxf + full[1]);
        float gv = tanh_(gxg + full[2]);
        float ov = sigf (gxo + full[3]);
        c = fv * c + iv * gv;
        hval = ov * tanh_(c);

        hsh[cb ^ 1][kh][gb] = __float2half(hval);
        __syncthreads();

        gxi = ni; gxf = nf; gxg = ng; gxo = no;
    }
    g_ctx[mypath * 256 + dir * 128 + gb] = hval;
}

// ---------------- phase D: attention -----------------------------------------
__global__ void __launch_bounds__(256) att1_kernel(const float* __restrict__ d1b,
                                                   const float* __restrict__ d2w,
                                                   const float* __restrict__ d2b) {
    __shared__ float cat[512];
    __shared__ float red[256];
    int p = blockIdx.x, tid = threadIdx.x;
    cat[tid]       = g_ctx[p * 256 + tid];
    cat[256 + tid] = g_u[tid];
    __syncthreads();
    float acc = d1b[tid];
#pragma unroll 8
    for (int k = 0; k < 512; k++) acc += cat[k] * g_d1wT[k * 256 + tid];
    red[tid] = tanh_(acc) * d2w[tid];
    __syncthreads();
    for (int s = 128; s > 0; s >>= 1) {
        if (tid < s) red[tid] += red[tid + s];
        __syncthreads();
    }
    if (tid == 0) g_score[p] = red[0] + d2b[0];
}

__global__ void __launch_bounds__(256) att2_kernel(const float* __restrict__ d1b) {
    __shared__ float al[128];
    __shared__ float red[128];
    __shared__ float cat[512];
    int tid = threadIdx.x;
    cat[tid] = g_u[tid];
    if (tid < 128) red[tid] = g_score[tid];
    __syncthreads();
    for (int s = 64; s > 0; s >>= 1) {
        if (tid < s) red[tid] = fmaxf(red[tid], red[tid + s]);
        __syncthreads();
    }
    float m = red[0];
    __syncthreads();
    if (tid < 128) { float e = __expf(g_score[tid] - m); al[tid] = e; red[tid] = e; }
    __syncthreads();
    for (int s = 64; s > 0; s >>= 1) {
        if (tid < s) red[tid] += red[tid + s];
        __syncthreads();
    }
    float inv = __fdividef(1.f, red[0]);
    float o = 0.f;
#pragma unroll 8
    for (int p = 0; p < 128; p++) o += al[p] * g_ctx[p * 256 + tid];
    cat[256 + tid] = o * inv;
    __syncthreads();
    float acc = d1b[tid];
#pragma unroll 8
    for (int k = 0; k < 512; k++) acc += cat[k] * g_d1wT[k * 256 + tid];
    __syncthreads();
    g_u[tid] = acc;
}

__global__ void __launch_bounds__(256) final_kernel(const float* __restrict__ d2w,
                                                    const float* __restrict__ d2b,
                                                    float* __restrict__ out) {
    __shared__ float red[256];
    int tid = threadIdx.x;
    red[tid] = fmaxf(g_u[tid], 0.f) * d2w[tid];
    __syncthreads();
    for (int s = 128; s > 0; s >>= 1) {
        if (tid < s) red[tid] += red[tid + s];
        __syncthreads();
    }
    if (tid == 0) out[0] = __fdividef(1.f, 1.f + __expf(-(red[0] + d2b[0])));
}

// ---------------- launch ------------------------------------------------------
extern "C" void kernel_launch(void* const* d_in, const int* in_sizes, int n_in,
                              void* d_out, int out_size) {
    const int*   path   = (const int*)  d_in[0];
    const int*   query  = (const int*)  d_in[1];
    const float* embA   = (const float*)d_in[2];
    const float* embB   = (const float*)d_in[3];
    const float* conv_w = (const float*)d_in[4];
    const float* conv_b = (const float*)d_in[5];
    const float* wihf   = (const float*)d_in[6];
    const float* whhf   = (const float*)d_in[7];
    const float* bihf   = (const float*)d_in[8];
    const float* bhhf   = (const float*)d_in[9];
    const float* wihb   = (const float*)d_in[10];
    const float* whhb   = (const float*)d_in[11];
    const float* bihb   = (const float*)d_in[12];
    const float* bhhb   = (const float*)d_in[13];
    const float* d1w    = (const float*)d_in[14];
    const float* d1b    = (const float*)d_in[15];
    const float* d2w    = (const float*)d_in[16];
    const float* d2b    = (const float*)d_in[17];
    float* out = (float*)d_out;

    const int gemm_smem = 2 * 128 * SROW * 2;          // 69632 B
    cudaFuncSetAttribute(gemm_kernel, cudaFuncAttributeMaxDynamicSharedMemorySize, gemm_smem);

    prep_kernel<<<1220, 256>>>(conv_w, d1w, wihf, wihb, bihf, bhhf, bihb, bhhb);
    init_u_kernel<<<1, 256>>>(query, embB);
    conv_kernel<<<dim3(16, 128), 128>>>(path, embA, conv_b);
    gemm_kernel<<<dim3(509, 8), 256, gemm_smem>>>();
    lstm_kernel<<<128, 256>>>(whhf, whhb);
    for (int it = 0; it < 2; it++) {
        att1_kernel<<<128, 256>>>(d1b, d2w, d2b);
        att2_kernel<<<1, 256>>>(d1b);
    }
    final_kernel<<<1, 256>>>(d2w, d2b, out);
}

// round 5
// speedup vs baseline: 3.0045x; 1.2938x over previous
#include <cuda_runtime.h>
#include <cuda_fp16.h>
#include <math.h>

#define Pn 128
#define Ln 512
#define En 256
#define Fn 128
#define Tn 509
#define SROW 136   // halves per smem row (272 B: ldmatrix conflict-free)

// ---------------- scratch (device globals; allocation is forbidden) ----------
__device__ __half  g_emb[(size_t)Pn * Ln * En];    // fp16 embedded tokens [p][l][e]
__device__ __half  g_conv[(size_t)Pn * 510 * Fn];  // conv+relu output [p][t'][f]
__device__ __half  g_xsh[(size_t)Pn * Tn * Fn];    // pooled conv output fp16 [p][t][f]
__device__ float   g_gx [(size_t)Pn * Tn * 1024];  // input gates [p*T][fwd512|bwd512]
__device__ float   g_ctx[Pn * En];                 // BiLSTM context [p][2H]
__device__ __half  g_cwh[Fn * 768];                // conv weights [f][w*256+e] fp16
__device__ float   g_d1wT[512 * 256];              // d1_w transposed [k][e]
__device__ __half  g_wh [1024 * 128];              // W_ih fp16 [n(fwd512|bwd512)][k]
__device__ float   g_bias[1024];                   // combined b_ih + b_hh
__device__ float   g_score[Pn];
__device__ float   g_u[En];

// ---------------- helpers ----------------------------------------------------
__device__ __forceinline__ float sigf(float x) {
    return __fdividef(1.f, 1.f + __expf(-x));
}
__device__ __forceinline__ float tanh_(float x) {
    return __fdividef(2.f, 1.f + __expf(-2.f * x)) - 1.f;
}
union UH { unsigned int u; __half2 h; };
__device__ __forceinline__ __half2 as_h2(unsigned int x) { UH v; v.u = x; return v.h; }

__device__ __forceinline__ void ldm_x4(unsigned& r0, unsigned& r1, unsigned& r2, unsigned& r3,
                                       unsigned addr) {
    asm volatile("ldmatrix.sync.aligned.m8n8.x4.shared.b16 {%0,%1,%2,%3}, [%4];"
                 : "=r"(r0), "=r"(r1), "=r"(r2), "=r"(r3) : "r"(addr));
}
__device__ __forceinline__ void mma16816(float* c, const unsigned* a, unsigned b0, unsigned b1) {
    asm volatile("mma.sync.aligned.m16n8k16.row.col.f32.f16.f16.f32 "
                 "{%0,%1,%2,%3}, {%4,%5,%6,%7}, {%8,%9}, {%0,%1,%2,%3};"
                 : "+f"(c[0]), "+f"(c[1]), "+f"(c[2]), "+f"(c[3])
                 : "r"(a[0]), "r"(a[1]), "r"(a[2]), "r"(a[3]), "r"(b0), "r"(b1));
}

// ---------------- prep: weight reshapes --------------------------------------
__global__ void prep_kernel(const float* __restrict__ conv_w,
                            const float* __restrict__ d1w,
                            const float* __restrict__ wihf, const float* __restrict__ wihb,
                            const float* __restrict__ bihf, const float* __restrict__ bhhf,
                            const float* __restrict__ bihb, const float* __restrict__ bhhb) {
    int idx = blockIdx.x * blockDim.x + threadIdx.x;
    if (idx < 98304) {                        // cwh[f][w*256+e] = conv_w[f][e][w]
        int f = idx / 768, r = idx - f * 768;
        int w = r >> 8, e = r & 255;
        g_cwh[idx] = __float2half(conv_w[(size_t)f * 768 + e * 3 + w]);
    } else if (idx < 98304 + 131072) {        // d1wT[k*256+e]
        int j = idx - 98304;
        int e = j & 255, k = j >> 8;
        g_d1wT[j] = d1w[(size_t)e * 512 + k];
    } else if (idx < 229376 + 131072) {       // g_wh[n][k] fp16
        int j = idx - 229376;
        int k = j & 127, n = j >> 7;
        float w = (n < 512) ? wihf[(size_t)n * 128 + k] : wihb[(size_t)(n - 512) * 128 + k];
        g_wh[j] = __float2half(w);
    } else if (idx < 360448 + 1024) {         // g_bias[n]
        int n = idx - 360448;
        g_bias[n] = (n < 512) ? (bihf[n] + bhhf[n]) : (bihb[n - 512] + bhhb[n - 512]);
    }
}

__global__ void init_u_kernel(const int* __restrict__ q,
                              const float* __restrict__ embB) {
    int t = threadIdx.x;
    g_u[t] = embB[(size_t)q[0] * En + t];
}

// ---------------- phase A0: embedding gather (fp32 -> fp16) -------------------
// grid (256, 128), block 256: block handles tokens l = bx*2, bx*2+1 of path by
__global__ void __launch_bounds__(256) embed_kernel(const int* __restrict__ path,
                                                    const float* __restrict__ embA) {
    int p = blockIdx.y;
    int l = blockIdx.x * 2 + (threadIdx.x >> 7);
    int t = threadIdx.x & 127;
    int tok = path[p * Ln + l];
    float2 v = *(const float2*)(embA + (size_t)tok * En + 2 * t);
    *(__half2*)(g_emb + ((size_t)p * Ln + l) * En + 2 * t) = __float22half2_rn(v);
}

// ---------------- phase A1: conv as GEMM (tensor cores) -----------------------
// conv[row][f] = emb_window[row][:768] . cwh[f][:768] ; rows = 65280 (p*510+t)
// A row for (p,t) = g_emb + (p*512+t)*256, span 768 halves (sliding window).
// grid (510), block 256; CTA tile 128x128, K-loop 6 x 128.
__global__ void __launch_bounds__(256) convgemm_kernel(const float* __restrict__ conv_b) {
    extern __shared__ __half smh[];
    __half* As = smh;                 // [128 m][SROW]
    __half* Bs = smh + 128 * SROW;    // [128 f][SROW]
    __shared__ float bias_s[128];

    int row0 = blockIdx.x * 128;
    int tid  = threadIdx.x;
    int wid  = tid >> 5, lane = tid & 31;
    int m0 = (wid >> 2) * 64;
    int n0 = (wid & 3) * 32;

    if (tid < 128) bias_s[tid] = conv_b[tid];

    unsigned sbase = (unsigned)__cvta_generic_to_shared(smh);
    unsigned aAddr[4], bAddr[2];
#pragma unroll
    for (int mi = 0; mi < 4; mi++) {
        int r = m0 + mi * 16 + (lane & 15);
        int ch = (lane >> 4) * 8;
        aAddr[mi] = sbase + (r * SROW + ch) * 2;
    }
#pragma unroll
    for (int bj = 0; bj < 2; bj++) {
        int r = n0 + bj * 16 + (lane & 7) + ((lane >> 4) << 3);
        int ch = ((lane >> 3) & 1) * 8;
        bAddr[bj] = sbase + (128 * SROW + r * SROW + ch) * 2;
    }

    float acc[4][4][4];
#pragma unroll
    for (int mi = 0; mi < 4; mi++)
#pragma unroll
        for (int nj = 0; nj < 4; nj++)
#pragma unroll
            for (int q = 0; q < 4; q++) acc[mi][nj][q] = 0.f;

    // per-thread A-load row pointer (8 rows per thread, strided by 32)
    for (int kt = 0; kt < 6; kt++) {
        int k0 = kt * 128;
        if (kt) __syncthreads();
        for (int idx = tid; idx < 2048; idx += 256) {
            int rr = idx >> 4, c = idx & 15;
            int gr = row0 + rr;
            int p = gr / 510, t = gr - p * 510;
            const uint4* asrc = (const uint4*)(g_emb + ((size_t)p * Ln + t) * En + k0);
            *(uint4*)(As + rr * SROW + c * 8) = asrc[c];
            const uint4* bsrc = (const uint4*)(g_cwh + (size_t)rr * 768 + k0);
            *(uint4*)(Bs + rr * SROW + c * 8) = bsrc[c];
        }
        __syncthreads();

#pragma unroll
        for (int ks = 0; ks < 8; ks++) {
            unsigned a[4][4], b[2][4];
#pragma unroll
            for (int mi = 0; mi < 4; mi++)
                ldm_x4(a[mi][0], a[mi][1], a[mi][2], a[mi][3], aAddr[mi] + ks * 32);
#pragma unroll
            for (int bj = 0; bj < 2; bj++)
                ldm_x4(b[bj][0], b[bj][1], b[bj][2], b[bj][3], bAddr[bj] + ks * 32);
#pragma unroll
            for (int mi = 0; mi < 4; mi++)
#pragma unroll
                for (int nj = 0; nj < 4; nj++)
                    mma16816(acc[mi][nj], a[mi], b[nj >> 1][(nj & 1) * 2], b[nj >> 1][(nj & 1) * 2 + 1]);
        }
    }

    // epilogue: +bias, relu, fp16 store to g_conv
    int qr = lane >> 2, qc = (lane & 3) * 2;
#pragma unroll
    for (int mi = 0; mi < 4; mi++) {
#pragma unroll
        for (int nj = 0; nj < 4; nj++) {
            int cc = n0 + nj * 8 + qc;
            float bx = bias_s[cc], by = bias_s[cc + 1];
            int r1 = row0 + m0 + mi * 16 + qr;
            __half2 v0 = __floats2half2_rn(fmaxf(acc[mi][nj][0] + bx, 0.f),
                                           fmaxf(acc[mi][nj][1] + by, 0.f));
            *(__half2*)(g_conv + (size_t)r1 * 128 + cc) = v0;
            __half2 v1 = __floats2half2_rn(fmaxf(acc[mi][nj][2] + bx, 0.f),
                                           fmaxf(acc[mi][nj][3] + by, 0.f));
            *(__half2*)(g_conv + (size_t)(r1 + 8) * 128 + cc) = v1;
        }
    }
}

// ---------------- phase A2: maxpool(2, stride 1) ------------------------------
__global__ void __launch_bounds__(256) pool_kernel() {
    int idx = blockIdx.x * blockDim.x + threadIdx.x;   // over Pn*Tn*64 half2
    if (idx >= Pn * Tn * 64) return;
    int c2 = idx & 63;
    int r  = idx >> 6;            // p*509 + t
    int p  = r / Tn, t = r - p * Tn;
    const __half2* src = (const __half2*)g_conv + ((size_t)p * 510 + t) * 64 + c2;
    __half2 v = __hmax2(src[0], src[64]);
    ((__half2*)g_xsh)[(size_t)r * 64 + c2] = v;
}

// ---------------- phase B: input-gate GEMM (tensor cores) ---------------------
__global__ void __launch_bounds__(256) gemm_kernel() {
    extern __shared__ __half smh[];
    __half* As = smh;                 // [128 m][SROW]
    __half* Bs = smh + 128 * SROW;    // [128 n][SROW]
    __shared__ float bias_s[128];

    int row0 = blockIdx.x * 128;
    int col0 = blockIdx.y * 128;
    int tid  = threadIdx.x;
    int wid  = tid >> 5, lane = tid & 31;
    int m0 = (wid >> 2) * 64;
    int n0 = (wid & 3) * 32;

    if (tid < 128) bias_s[tid] = g_bias[col0 + tid];

    {
        const uint4* asrc = (const uint4*)(g_xsh + (size_t)row0 * 128);
        const uint4* bsrc = (const uint4*)(g_wh + (size_t)col0 * 128);
        for (int idx = tid; idx < 2048; idx += 256) {
            int r = idx >> 4, c = idx & 15;
            *(uint4*)(As + r * SROW + c * 8) = asrc[r * 16 + c];
            *(uint4*)(Bs + r * SROW + c * 8) = bsrc[r * 16 + c];
        }
    }
    __syncthreads();

    unsigned sbase = (unsigned)__cvta_generic_to_shared(smh);
    unsigned aAddr[4], bAddr[2];
#pragma unroll
    for (int mi = 0; mi < 4; mi++) {
        int r = m0 + mi * 16 + (lane & 15);
        int ch = (lane >> 4) * 8;
        aAddr[mi] = sbase + (r * SROW + ch) * 2;
    }
#pragma unroll
    for (int bj = 0; bj < 2; bj++) {
        int r = n0 + bj * 16 + (lane & 7) + ((lane >> 4) << 3);
        int ch = ((lane >> 3) & 1) * 8;
        bAddr[bj] = sbase + (128 * SROW + r * SROW + ch) * 2;
    }

    float acc[4][4][4];
#pragma unroll
    for (int mi = 0; mi < 4; mi++)
#pragma unroll
        for (int nj = 0; nj < 4; nj++)
#pragma unroll
            for (int q = 0; q < 4; q++) acc[mi][nj][q] = 0.f;

#pragma unroll
    for (int ks = 0; ks < 8; ks++) {
        unsigned a[4][4], b[2][4];
#pragma unroll
        for (int mi = 0; mi < 4; mi++)
            ldm_x4(a[mi][0], a[mi][1], a[mi][2], a[mi][3], aAddr[mi] + ks * 32);
#pragma unroll
        for (int bj = 0; bj < 2; bj++)
            ldm_x4(b[bj][0], b[bj][1], b[bj][2], b[bj][3], bAddr[bj] + ks * 32);
#pragma unroll
        for (int mi = 0; mi < 4; mi++)
#pragma unroll
            for (int nj = 0; nj < 4; nj++)
                mma16816(acc[mi][nj], a[mi], b[nj >> 1][(nj & 1) * 2], b[nj >> 1][(nj & 1) * 2 + 1]);
    }

    int qr = lane >> 2, qc = (lane & 3) * 2;
#pragma unroll
    for (int mi = 0; mi < 4; mi++) {
#pragma unroll
        for (int nj = 0; nj < 4; nj++) {
            int cc = n0 + nj * 8 + qc;
            float bx = bias_s[cc], by = bias_s[cc + 1];
            size_t base = (size_t)(row0 + m0 + mi * 16 + qr) * 1024 + col0 + cc;
            *(float2*)(g_gx + base) = make_float2(acc[mi][nj][0] + bx, acc[mi][nj][1] + by);
            size_t base2 = base + (size_t)8 * 1024;
            *(float2*)(g_gx + base2) = make_float2(acc[mi][nj][2] + bx, acc[mi][nj][3] + by);
        }
    }
}

// ---------------- phase C: LSTM recurrence (register-resident weights) --------
__global__ void __launch_bounds__(256, 1) lstm_kernel(const float* __restrict__ whhf,
                                                      const float* __restrict__ whhb) {
    __shared__ __align__(16) __half hsh[2][2][136];   // [buf][seq][h]

    int bid  = blockIdx.x;
    int dir  = bid & 1;
    int pair = bid >> 1;
    int tid  = threadIdx.x;
    int gb   = tid >> 1;
    int kh   = tid & 1;

    const float* whh = dir ? whhb : whhf;

    __half2 wreg[4][32];
#pragma unroll
    for (int g = 0; g < 4; g++) {
        const float2* wp = (const float2*)(whh + (size_t)(gb + g * 128) * 128 + kh * 64);
#pragma unroll
        for (int j = 0; j < 32; j++) wreg[g][j] = __float22half2_rn(wp[j]);
    }

    if (tid < 136) {
        hsh[0][0][tid] = __float2half(0.f); hsh[0][1][tid] = __float2half(0.f);
        hsh[1][0][tid] = __float2half(0.f); hsh[1][1][tid] = __float2half(0.f);
    }
    __syncthreads();

    int mypath = pair * 2 + kh;
    const float* gxbase = g_gx + (size_t)mypath * Tn * 1024 + dir * 512 + gb;

    float c = 0.f, hval = 0.f;
    const __half2 z = __float2half2_rn(0.f);

    int tt0 = dir ? (Tn - 1) : 0;
    const float* gp0 = gxbase + (size_t)tt0 * 1024;
    float gxi = gp0[0], gxf = gp0[128], gxg = gp0[256], gxo = gp0[384];

    for (int s = 0; s < Tn; s++) {
        int sn = (s + 1 < Tn) ? s + 1 : s;
        int ttn = dir ? (Tn - 1 - sn) : sn;
        const float* gn = gxbase + (size_t)ttn * 1024;
        float ni = gn[0], nf = gn[128], ng = gn[256], no = gn[384];

        int cb = s & 1;
        float sA[4], sB[4];
        {
            const uint4* h4 = (const uint4*)(&hsh[cb][0][kh * 64]);
            __half2 a0 = z, a1 = z, a2 = z, a3 = z;
            float f0 = 0.f, f1 = 0.f, f2 = 0.f, f3 = 0.f;
#pragma unroll
            for (int q = 0; q < 8; q++) {
                uint4 hv = h4[q];
                __half2 h0 = as_h2(hv.x), h1 = as_h2(hv.y), h2v = as_h2(hv.z), h3 = as_h2(hv.w);
                a0 = __hfma2(wreg[0][q*4+0], h0, a0); a0 = __hfma2(wreg[0][q*4+1], h1, a0);
                a0 = __hfma2(wreg[0][q*4+2], h2v, a0); a0 = __hfma2(wreg[0][q*4+3], h3, a0);
                a1 = __hfma2(wreg[1][q*4+0], h0, a1); a1 = __hfma2(wreg[1][q*4+1], h1, a1);
                a1 = __hfma2(wreg[1][q*4+2], h2v, a1); a1 = __hfma2(wreg[1][q*4+3], h3, a1);
                a2 = __hfma2(wreg[2][q*4+0], h0, a2); a2 = __hfma2(wreg[2][q*4+1], h1, a2);
                a2 = __hfma2(wreg[2][q*4+2], h2v, a2); a2 = __hfma2(wreg[2][q*4+3], h3, a2);
                a3 = __hfma2(wreg[3][q*4+0], h0, a3); a3 = __hfma2(wreg[3][q*4+1], h1, a3);
                a3 = __hfma2(wreg[3][q*4+2], h2v, a3); a3 = __hfma2(wreg[3][q*4+3], h3, a3);
                if (q == 3 || q == 7) {
                    float2 t;
                    t = __half22float2(a0); f0 += t.x + t.y; a0 = z;
                    t = __half22float2(a1); f1 += t.x + t.y; a1 = z;
                    t = __half22float2(a2); f2 += t.x + t.y; a2 = z;
                    t = __half22float2(a3); f3 += t.x + t.y; a3 = z;
                }
            }
            sA[0] = f0; sA[1] = f1; sA[2] = f2; sA[3] = f3;
        }
        {
            const uint4* h4 = (const uint4*)(&hsh[cb][1][kh * 64]);
            __half2 a0 = z, a1 = z, a2 = z, a3 = z;
            float f0 = 0.f, f1 = 0.f, f2 = 0.f, f3 = 0.f;
#pragma unroll
            for (int q = 0; q < 8; q++) {
                uint4 hv = h4[q];
                __half2 h0 = as_h2(hv.x), h1 = as_h2(hv.y), h2v = as_h2(hv.z), h3 = as_h2(hv.w);
                a0 = __hfma2(wreg[0][q*4+0], h0, a0); a0 = __hfma2(wreg[0][q*4+1], h1, a0);
                a0 = __hfma2(wreg[0][q*4+2], h2v, a0); a0 = __hfma2(wreg[0][q*4+3], h3, a0);
                a1 = __hfma2(wreg[1][q*4+0], h0, a1); a1 = __hfma2(wreg[1][q*4+1], h1, a1);
                a1 = __hfma2(wreg[1][q*4+2], h2v, a1); a1 = __hfma2(wreg[1][q*4+3], h3, a1);
                a2 = __hfma2(wreg[2][q*4+0], h0, a2); a2 = __hfma2(wreg[2][q*4+1], h1, a2);
                a2 = __hfma2(wreg[2][q*4+2], h2v, a2); a2 = __hfma2(wreg[2][q*4+3], h3, a2);
                a3 = __hfma2(wreg[3][q*4+0], h0, a3); a3 = __hfma2(wreg[3][q*4+1], h1, a3);
                a3 = __hfma2(wreg[3][q*4+2], h2v, a3); a3 = __hfma2(wreg[3][q*4+3], h3, a3);
                if (q == 3 || q == 7) {
                    float2 t;
                    t = __half22float2(a0); f0 += t.x + t.y; a0 = z;
                    t = __half22float2(a1); f1 += t.x + t.y; a1 = z;
                    t = __half22float2(a2); f2 += t.x + t.y; a2 = z;
                    t = __half22float2(a3); f3 += t.x + t.y; a3 = z;
                }
            }
            sB[0] = f0; sB[1] = f1; sB[2] = f2; sB[3] = f3;
        }

        float full[4];
#pragma unroll
        for (int g = 0; g < 4; g++) {
            float own   = kh ? sB[g] : sA[g];
            float other = kh ? sA[g] : sB[g];
            full[g] = own + __shfl_xor_sync(0xffffffffu, other, 1);
        }

        float iv = sigf (gxi + full[0]);
        float fv = sigf (gxf + full[1]);
        float gv = tanh_(gxg + full[2]);
        float ov = sigf (gxo + full[3]);
        c = fv * c + iv * gv;
        hval = ov * tanh_(c);

        hsh[cb ^ 1][kh][gb] = __float2half(hval);
        __syncthreads();

        gxi = ni; gxf = nf; gxg = ng; gxo = no;
    }
    g_ctx[mypath * 256 + dir * 128 + gb] = hval;
}

// ---------------- phase D: attention -----------------------------------------
__global__ void __launch_bounds__(256) att1_kernel(const float* __restrict__ d1b,
                                                   const float* __restrict__ d2w,
                                                   const float* __restrict__ d2b) {
    __shared__ float cat[512];
    __shared__ float red[256];
    int p = blockIdx.x, tid = threadIdx.x;
    cat[tid]       = g_ctx[p * 256 + tid];
    cat[256 + tid] = g_u[tid];
    __syncthreads();
    float acc = d1b[tid];
#pragma unroll 8
    for (int k = 0; k < 512; k++) acc += cat[k] * g_d1wT[k * 256 + tid];
    red[tid] = tanh_(acc) * d2w[tid];
    __syncthreads();
    for (int s = 128; s > 0; s >>= 1) {
        if (tid < s) red[tid] += red[tid + s];
        __syncthreads();
    }
    if (tid == 0) g_score[p] = red[0] + d2b[0];
}

__global__ void __launch_bounds__(256) att2_kernel(const float* __restrict__ d1b) {
    __shared__ float al[128];
    __shared__ float red[128];
    __shared__ float cat[512];
    int tid = threadIdx.x;
    cat[tid] = g_u[tid];
    if (tid < 128) red[tid] = g_score[tid];
    __syncthreads();
    for (int s = 64; s > 0; s >>= 1) {
        if (tid < s) red[tid] = fmaxf(red[tid], red[tid + s]);
        __syncthreads();
    }
    float m = red[0];
    __syncthreads();
    if (tid < 128) { float e = __expf(g_score[tid] - m); al[tid] = e; red[tid] = e; }
    __syncthreads();
    for (int s = 64; s > 0; s >>= 1) {
        if (tid < s) red[tid] += red[tid + s];
        __syncthreads();
    }
    float inv = __fdividef(1.f, red[0]);
    float o = 0.f;
#pragma unroll 8
    for (int p = 0; p < 128; p++) o += al[p] * g_ctx[p * 256 + tid];
    cat[256 + tid] = o * inv;
    __syncthreads();
    float acc = d1b[tid];
#pragma unroll 8
    for (int k = 0; k < 512; k++) acc += cat[k] * g_d1wT[k * 256 + tid];
    __syncthreads();
    g_u[tid] = acc;
}

__global__ void __launch_bounds__(256) final_kernel(const float* __restrict__ d2w,
                                                    const float* __restrict__ d2b,
                                                    float* __restrict__ out) {
    __shared__ float red[256];
    int tid = threadIdx.x;
    red[tid] = fmaxf(g_u[tid], 0.f) * d2w[tid];
    __syncthreads();
    for (int s = 128; s > 0; s >>= 1) {
        if (tid < s) red[tid] += red[tid + s];
        __syncthreads();
    }
    if (tid == 0) out[0] = __fdividef(1.f, 1.f + __expf(-(red[0] + d2b[0])));
}

// ---------------- launch ------------------------------------------------------
extern "C" void kernel_launch(void* const* d_in, const int* in_sizes, int n_in,
                              void* d_out, int out_size) {
    const int*   path   = (const int*)  d_in[0];
    const int*   query  = (const int*)  d_in[1];
    const float* embA   = (const float*)d_in[2];
    const float* embB   = (const float*)d_in[3];
    const float* conv_w = (const float*)d_in[4];
    const float* conv_b = (const float*)d_in[5];
    const float* wihf   = (const float*)d_in[6];
    const float* whhf   = (const float*)d_in[7];
    const float* bihf   = (const float*)d_in[8];
    const float* bhhf   = (const float*)d_in[9];
    const float* wihb   = (const float*)d_in[10];
    const float* whhb   = (const float*)d_in[11];
    const float* bihb   = (const float*)d_in[12];
    const float* bhhb   = (const float*)d_in[13];
    const float* d1w    = (const float*)d_in[14];
    const float* d1b    = (const float*)d_in[15];
    const float* d2w    = (const float*)d_in[16];
    const float* d2b    = (const float*)d_in[17];
    float* out = (float*)d_out;

    const int mma_smem = 2 * 128 * SROW * 2;           // 69632 B
    cudaFuncSetAttribute(gemm_kernel, cudaFuncAttributeMaxDynamicSharedMemorySize, mma_smem);
    cudaFuncSetAttribute(convgemm_kernel, cudaFuncAttributeMaxDynamicSharedMemorySize, mma_smem);

    prep_kernel<<<1412, 256>>>(conv_w, d1w, wihf, wihb, bihf, bhhf, bihb, bhhb);
    init_u_kernel<<<1, 256>>>(query, embB);
    embed_kernel<<<dim3(256, 128), 256>>>(path, embA);
    convgemm_kernel<<<510, 256, mma_smem>>>(conv_b);
    pool_kernel<<<(Pn * Tn * 64 + 255) / 256, 256>>>();
    gemm_kernel<<<dim3(509, 8), 256, mma_smem>>>();
    lstm_kernel<<<128, 256>>>(whhf, whhb);
    for (int it = 0; it < 2; it++) {
        att1_kernel<<<128, 256>>>(d1b, d2w, d2b);
        att2_kernel<<<1, 256>>>(d1b);
    }
    final_kernel<<<1, 256>>>(d2w, d2b, out);
}

// round 6
// speedup vs baseline: 3.0546x; 1.0167x over previous
#include <cuda_runtime.h>
#include <cuda_fp16.h>
#include <math.h>

#define Pn 128
#define Ln 512
#define En 256
#define Fn 128
#define Tn 509
#define SROW 136   // halves per smem row (272 B: ldmatrix conflict-free)

// ---------------- scratch (device globals; allocation is forbidden) ----------
__device__ __half  g_emb[(size_t)Pn * Ln * En];    // fp16 embedded tokens [p][l][e]
__device__ __half  g_conv[(size_t)Pn * 510 * Fn];  // conv+relu output [p][t'][f]
__device__ __half  g_gxh[(size_t)Pn * Tn * 1024];  // input gates fp16 [p*T][fwd512|bwd512]
__device__ float   g_ctx[Pn * En];                 // BiLSTM context [p][2H]
__device__ __half  g_cwh[Fn * 768];                // conv weights [f][w*256+e] fp16
__device__ float   g_d1wT[512 * 256];              // d1_w transposed [k][e]
__device__ __half  g_wh [1024 * 128];              // W_ih fp16 [n(fwd512|bwd512)][k]
__device__ float   g_bias[1024];                   // combined b_ih + b_hh
__device__ float   g_score[Pn];
__device__ float   g_u[En];

// ---------------- helpers ----------------------------------------------------
__device__ __forceinline__ float sigf(float x) {
    return __fdividef(1.f, 1.f + __expf(-x));
}
__device__ __forceinline__ float tanh_(float x) {
    return __fdividef(2.f, 1.f + __expf(-2.f * x)) - 1.f;
}
union UH2 { unsigned int u; __half2 h; };
__device__ __forceinline__ unsigned h2u(__half2 h) { UH2 v; v.h = h; return v.u; }

__device__ __forceinline__ void ldm_x4(unsigned& r0, unsigned& r1, unsigned& r2, unsigned& r3,
                                       unsigned addr) {
    asm volatile("ldmatrix.sync.aligned.m8n8.x4.shared.b16 {%0,%1,%2,%3}, [%4];"
                 : "=r"(r0), "=r"(r1), "=r"(r2), "=r"(r3) : "r"(addr));
}
__device__ __forceinline__ void mma16816(float* c, const unsigned* a, unsigned b0, unsigned b1) {
    asm volatile("mma.sync.aligned.m16n8k16.row.col.f32.f16.f16.f32 "
                 "{%0,%1,%2,%3}, {%4,%5,%6,%7}, {%8,%9}, {%0,%1,%2,%3};"
                 : "+f"(c[0]), "+f"(c[1]), "+f"(c[2]), "+f"(c[3])
                 : "r"(a[0]), "r"(a[1]), "r"(a[2]), "r"(a[3]), "r"(b0), "r"(b1));
}

// ---------------- launch 1: setup (prep + init_u + embed fused) ---------------
#define PREP_BLKS 1412
__global__ void __launch_bounds__(256) setup_kernel(
        const int* __restrict__ path, const int* __restrict__ query,
        const float* __restrict__ embA, const float* __restrict__ embB,
        const float* __restrict__ conv_w, const float* __restrict__ d1w,
        const float* __restrict__ wihf, const float* __restrict__ wihb,
        const float* __restrict__ bihf, const float* __restrict__ bhhf,
        const float* __restrict__ bihb, const float* __restrict__ bhhb) {
    int bx = blockIdx.x;
    if (bx < PREP_BLKS) {
        int idx = bx * 256 + threadIdx.x;
        if (idx < 98304) {                        // cwh[f][w*256+e] = conv_w[f][e][w]
            int f = idx / 768, r = idx - f * 768;
            int w = r >> 8, e = r & 255;
            g_cwh[idx] = __float2half(conv_w[(size_t)f * 768 + e * 3 + w]);
        } else if (idx < 98304 + 131072) {        // d1wT[k*256+e]
            int j = idx - 98304;
            int e = j & 255, k = j >> 8;
            g_d1wT[j] = d1w[(size_t)e * 512 + k];
        } else if (idx < 229376 + 131072) {       // g_wh[n][k] fp16
            int j = idx - 229376;
            int k = j & 127, n = j >> 7;
            float w = (n < 512) ? wihf[(size_t)n * 128 + k] : wihb[(size_t)(n - 512) * 128 + k];
            g_wh[j] = __float2half(w);
        } else if (idx < 360448 + 1024) {         // g_bias[n]
            int n = idx - 360448;
            g_bias[n] = (n < 512) ? (bihf[n] + bhhf[n]) : (bihb[n - 512] + bhhb[n - 512]);
        }
    } else if (bx < PREP_BLKS + 32768) {          // embedding gather
        int b = bx - PREP_BLKS;
        int p = b >> 8;
        int l = (b & 255) * 2 + (threadIdx.x >> 7);
        int t = threadIdx.x & 127;
        int tok = path[p * Ln + l];
        float2 v = *(const float2*)(embA + (size_t)tok * En + 2 * t);
        *(__half2*)(g_emb + ((size_t)p * Ln + l) * En + 2 * t) = __float22half2_rn(v);
    } else {                                      // init u
        g_u[threadIdx.x] = embB[(size_t)query[0] * En + threadIdx.x];
    }
}

// ---------------- launch 2: conv as GEMM (tensor cores) -----------------------
__global__ void __launch_bounds__(256) convgemm_kernel(const float* __restrict__ conv_b) {
    extern __shared__ __half smh[];
    __half* As = smh;                 // [128 m][SROW]
    __half* Bs = smh + 128 * SROW;    // [128 f][SROW]
    __shared__ float bias_s[128];

    int row0 = blockIdx.x * 128;
    int tid  = threadIdx.x;
    int wid  = tid >> 5, lane = tid & 31;
    int m0 = (wid >> 2) * 64;
    int n0 = (wid & 3) * 32;

    if (tid < 128) bias_s[tid] = conv_b[tid];

    unsigned sbase = (unsigned)__cvta_generic_to_shared(smh);
    unsigned aAddr[4], bAddr[2];
#pragma unroll
    for (int mi = 0; mi < 4; mi++) {
        int r = m0 + mi * 16 + (lane & 15);
        int ch = (lane >> 4) * 8;
        aAddr[mi] = sbase + (r * SROW + ch) * 2;
    }
#pragma unroll
    for (int bj = 0; bj < 2; bj++) {
        int r = n0 + bj * 16 + (lane & 7) + ((lane >> 4) << 3);
        int ch = ((lane >> 3) & 1) * 8;
        bAddr[bj] = sbase + (128 * SROW + r * SROW + ch) * 2;
    }

    float acc[4][4][4];
#pragma unroll
    for (int mi = 0; mi < 4; mi++)
#pragma unroll
        for (int nj = 0; nj < 4; nj++)
#pragma unroll
            for (int q = 0; q < 4; q++) acc[mi][nj][q] = 0.f;

    for (int kt = 0; kt < 6; kt++) {
        int k0 = kt * 128;
        if (kt) __syncthreads();
        for (int idx = tid; idx < 2048; idx += 256) {
            int rr = idx >> 4, c = idx & 15;
            int gr = row0 + rr;
            int p = gr / 510, t = gr - p * 510;
            const uint4* asrc = (const uint4*)(g_emb + ((size_t)p * Ln + t) * En + k0);
            *(uint4*)(As + rr * SROW + c * 8) = asrc[c];
            const uint4* bsrc = (const uint4*)(g_cwh + (size_t)rr * 768 + k0);
            *(uint4*)(Bs + rr * SROW + c * 8) = bsrc[c];
        }
        __syncthreads();

#pragma unroll
        for (int ks = 0; ks < 8; ks++) {
            unsigned a[4][4], b[2][4];
#pragma unroll
            for (int mi = 0; mi < 4; mi++)
                ldm_x4(a[mi][0], a[mi][1], a[mi][2], a[mi][3], aAddr[mi] + ks * 32);
#pragma unroll
            for (int bj = 0; bj < 2; bj++)
                ldm_x4(b[bj][0], b[bj][1], b[bj][2], b[bj][3], bAddr[bj] + ks * 32);
#pragma unroll
            for (int mi = 0; mi < 4; mi++)
#pragma unroll
                for (int nj = 0; nj < 4; nj++)
                    mma16816(acc[mi][nj], a[mi], b[nj >> 1][(nj & 1) * 2], b[nj >> 1][(nj & 1) * 2 + 1]);
        }
    }

    int qr = lane >> 2, qc = (lane & 3) * 2;
#pragma unroll
    for (int mi = 0; mi < 4; mi++) {
#pragma unroll
        for (int nj = 0; nj < 4; nj++) {
            int cc = n0 + nj * 8 + qc;
            float bx = bias_s[cc], by = bias_s[cc + 1];
            int r1 = row0 + m0 + mi * 16 + qr;
            __half2 v0 = __floats2half2_rn(fmaxf(acc[mi][nj][0] + bx, 0.f),
                                           fmaxf(acc[mi][nj][1] + by, 0.f));
            *(__half2*)(g_conv + (size_t)r1 * 128 + cc) = v0;
            __half2 v1 = __floats2half2_rn(fmaxf(acc[mi][nj][2] + bx, 0.f),
                                           fmaxf(acc[mi][nj][3] + by, 0.f));
            *(__half2*)(g_conv + (size_t)(r1 + 8) * 128 + cc) = v1;
        }
    }
}

// ---------------- launch 3: input-gate GEMM (pool fused into A-load) ----------
// gx[row=(p,t)][n] = maxpool(conv)[p][t][:] . W[n][:] + bias[n]; rows = 65152
__global__ void __launch_bounds__(256) gemm_kernel() {
    extern __shared__ __half smh[];
    __half* As = smh;                 // [128 m][SROW]
    __half* Bs = smh + 128 * SROW;    // [128 n][SROW]
    __shared__ float bias_s[128];

    int row0 = blockIdx.x * 128;
    int col0 = blockIdx.y * 128;
    int tid  = threadIdx.x;
    int wid  = tid >> 5, lane = tid & 31;
    int m0 = (wid >> 2) * 64;
    int n0 = (wid & 3) * 32;

    if (tid < 128) bias_s[tid] = g_bias[col0 + tid];

    {
        const uint4* bsrc = (const uint4*)(g_wh + (size_t)col0 * 128);
        for (int idx = tid; idx < 2048; idx += 256) {
            int r = idx >> 4, c = idx & 15;
            int gr = row0 + r;
            int p = gr / Tn, t = gr - p * Tn;
            // fused maxpool(2,1): rows t and t+1 of conv output
            const uint4* csrc = (const uint4*)(g_conv + ((size_t)p * 510 + t) * 128);
            uint4 x = csrc[c], y = csrc[c + 16];
            UH2 ax, ay, r0, r1, r2, r3;
            ax.u = x.x; ay.u = y.x; r0.h = __hmax2(ax.h, ay.h);
            ax.u = x.y; ay.u = y.y; r1.h = __hmax2(ax.h, ay.h);
            ax.u = x.z; ay.u = y.z; r2.h = __hmax2(ax.h, ay.h);
            ax.u = x.w; ay.u = y.w; r3.h = __hmax2(ax.h, ay.h);
            uint4 m4 = make_uint4(r0.u, r1.u, r2.u, r3.u);
            *(uint4*)(As + r * SROW + c * 8) = m4;
            *(uint4*)(Bs + r * SROW + c * 8) = bsrc[r * 16 + c];
        }
    }
    __syncthreads();

    unsigned sbase = (unsigned)__cvta_generic_to_shared(smh);
    unsigned aAddr[4], bAddr[2];
#pragma unroll
    for (int mi = 0; mi < 4; mi++) {
        int r = m0 + mi * 16 + (lane & 15);
        int ch = (lane >> 4) * 8;
        aAddr[mi] = sbase + (r * SROW + ch) * 2;
    }
#pragma unroll
    for (int bj = 0; bj < 2; bj++) {
        int r = n0 + bj * 16 + (lane & 7) + ((lane >> 4) << 3);
        int ch = ((lane >> 3) & 1) * 8;
        bAddr[bj] = sbase + (128 * SROW + r * SROW + ch) * 2;
    }

    float acc[4][4][4];
#pragma unroll
    for (int mi = 0; mi < 4; mi++)
#pragma unroll
        for (int nj = 0; nj < 4; nj++)
#pragma unroll
            for (int q = 0; q < 4; q++) acc[mi][nj][q] = 0.f;

#pragma unroll
    for (int ks = 0; ks < 8; ks++) {
        unsigned a[4][4], b[2][4];
#pragma unroll
        for (int mi = 0; mi < 4; mi++)
            ldm_x4(a[mi][0], a[mi][1], a[mi][2], a[mi][3], aAddr[mi] + ks * 32);
#pragma unroll
        for (int bj = 0; bj < 2; bj++)
            ldm_x4(b[bj][0], b[bj][1], b[bj][2], b[bj][3], bAddr[bj] + ks * 32);
#pragma unroll
        for (int mi = 0; mi < 4; mi++)
#pragma unroll
            for (int nj = 0; nj < 4; nj++)
                mma16816(acc[mi][nj], a[mi], b[nj >> 1][(nj & 1) * 2], b[nj >> 1][(nj & 1) * 2 + 1]);
    }

    int qr = lane >> 2, qc = (lane & 3) * 2;
#pragma unroll
    for (int mi = 0; mi < 4; mi++) {
#pragma unroll
        for (int nj = 0; nj < 4; nj++) {
            int cc = n0 + nj * 8 + qc;
            float bx = bias_s[cc], by = bias_s[cc + 1];
            size_t base = (size_t)(row0 + m0 + mi * 16 + qr) * 1024 + col0 + cc;
            *(__half2*)(g_gxh + base) = __floats2half2_rn(acc[mi][nj][0] + bx, acc[mi][nj][1] + by);
            *(__half2*)(g_gxh + base + 8 * 1024) = __floats2half2_rn(acc[mi][nj][2] + bx, acc[mi][nj][3] + by);
        }
    }
}

// ---------------- launch 4: LSTM recurrence (tensor cores) --------------------
// 64 CTAs: bid = (pgroup<<1)|dir; 4 paths per CTA; 512 threads (16 warps).
// Per step: preact[512 rows][4 paths] = W_hh (A, register-resident frags) x
// h^T (B via ldmatrix from smem hN[8 paths][136]). Pointwise: thread owns
// (unit = tid>>2, p = tid&3), fp32 c resident, h written back fp16 to hN.
__global__ void __launch_bounds__(512, 1) lstm_kernel(const float* __restrict__ whhf,
                                                      const float* __restrict__ whhb) {
    __shared__ float pre[512][8];                // 16 KB (cols 4-7 unused)
    __shared__ __align__(16) __half hN[8][136];  // [path][unit], padded rows

    int bid = blockIdx.x;
    int dir = bid & 1;
    int pg  = bid >> 1;
    int tid = threadIdx.x;
    int w   = tid >> 5, l = tid & 31;

    const float* whh = dir ? whhb : whhf;

    // A fragments: warp w owns gate-rows [w*32, w*32+32) as 2 m16 tiles x 8 k-chunks
    unsigned A[2][8][4];
    int rbase = w * 32;
#pragma unroll
    for (int mt = 0; mt < 2; mt++)
#pragma unroll
        for (int kc = 0; kc < 8; kc++) {
            int r = rbase + mt * 16 + (l >> 2);
            int k = kc * 16 + (l & 3) * 2;
            float2 v0 = *(const float2*)(whh + (size_t)r * 128 + k);
            float2 v1 = *(const float2*)(whh + (size_t)(r + 8) * 128 + k);
            float2 v2 = *(const float2*)(whh + (size_t)r * 128 + k + 8);
            float2 v3 = *(const float2*)(whh + (size_t)(r + 8) * 128 + k + 8);
            A[mt][kc][0] = h2u(__float22half2_rn(v0));
            A[mt][kc][1] = h2u(__float22half2_rn(v1));
            A[mt][kc][2] = h2u(__float22half2_rn(v2));
            A[mt][kc][3] = h2u(__float22half2_rn(v3));
        }

    // zero hN (1088 halves = 544 half2)
    if (tid < 544) ((__half2*)&hN[0][0])[tid] = __float2half2_rn(0.f);

    // pointwise ownership
    int u = tid >> 2, p = tid & 3;
    int pathg = pg * 4 + p;
    long stride = dir ? -1024 : 1024;
    const __half* gp = g_gxh + (size_t)pathg * Tn * 1024 + dir * 512 + u
                     + (dir ? (size_t)(Tn - 1) * 1024 : 0);
    float gi = __half2float(gp[0]),   gf = __half2float(gp[128]);
    float gg = __half2float(gp[256]), go = __half2float(gp[384]);

    float c = 0.f, hval = 0.f;
    unsigned sb = (unsigned)__cvta_generic_to_shared(&hN[0][0]);
    // ldmatrix lane address: matrix j = l>>3 (k block), row i = l&7 (path)
    unsigned ldaddr_base = sb + ((l & 7) * 136 + (l >> 3) * 8) * 2;

    __syncthreads();

    for (int s = 0; s < Tn; s++) {
        // prefetch next step's gx
        const __half* gn = gp + ((s + 1 < Tn) ? stride : 0);
        float ni = __half2float(gn[0]),   nf = __half2float(gn[128]);
        float ng = __half2float(gn[256]), no_ = __half2float(gn[384]);

        // B fragments from hN, then 16 mma (2 m-tiles x 8 k-chunks)
        unsigned b[8][2];
#pragma unroll
        for (int ks = 0; ks < 4; ks++) {
            unsigned r0, r1, r2, r3;
            ldm_x4(r0, r1, r2, r3, ldaddr_base + ks * 64);   // +32 halves per x4
            b[2 * ks][0] = r0;     b[2 * ks][1] = r1;
            b[2 * ks + 1][0] = r2; b[2 * ks + 1][1] = r3;
        }
        float C0[4] = {0.f, 0.f, 0.f, 0.f};
        float C1[4] = {0.f, 0.f, 0.f, 0.f};
#pragma unroll
        for (int kc = 0; kc < 8; kc++) {
            mma16816(C0, A[0][kc], b[kc][0], b[kc][1]);
            mma16816(C1, A[1][kc], b[kc][0], b[kc][1]);
        }

        // C -> pre smem (only cols 0-3 meaningful; all lanes store)
        {
            int rr = rbase + (l >> 2), cc = (l & 3) * 2;
            *(float2*)&pre[rr][cc]      = make_float2(C0[0], C0[1]);
            *(float2*)&pre[rr + 8][cc]  = make_float2(C0[2], C0[3]);
            *(float2*)&pre[rr + 16][cc] = make_float2(C1[0], C1[1]);
            *(float2*)&pre[rr + 24][cc] = make_float2(C1[2], C1[3]);
        }
        __syncthreads();

        float iv = sigf (gi + pre[u][p]);
        float fv = sigf (gf + pre[128 + u][p]);
        float gv = tanh_(gg + pre[256 + u][p]);
        float ov = sigf (go + pre[384 + u][p]);
        c = fv * c + iv * gv;
        hval = ov * tanh_(c);
        hN[p][u] = __float2half(hval);

        gi = ni; gf = nf; gg = ng; go = no_;
        gp = gn;
        __syncthreads();
    }
    g_ctx[pathg * 256 + dir * 128 + u] = hval;
}

// ---------------- attention --------------------------------------------------
__global__ void __launch_bounds__(256) att1_kernel(const float* __restrict__ d1b,
                                                   const float* __restrict__ d2w,
                                                   const float* __restrict__ d2b) {
    __shared__ float cat[512];
    __shared__ float red[256];
    int p = blockIdx.x, tid = threadIdx.x;
    cat[tid]       = g_ctx[p * 256 + tid];
    cat[256 + tid] = g_u[tid];
    __syncthreads();
    float acc = d1b[tid];
#pragma unroll 8
    for (int k = 0; k < 512; k++) acc += cat[k] * g_d1wT[k * 256 + tid];
    red[tid] = tanh_(acc) * d2w[tid];
    __syncthreads();
    for (int s = 128; s > 0; s >>= 1) {
        if (tid < s) red[tid] += red[tid + s];
        __syncthreads();
    }
    if (tid == 0) g_score[p] = red[0] + d2b[0];
}

__global__ void __launch_bounds__(256) att2_kernel(const float* __restrict__ d1b) {
    __shared__ float al[128];
    __shared__ float red[128];
    __shared__ float cat[512];
    int tid = threadIdx.x;
    cat[tid] = g_u[tid];
    if (tid < 128) red[tid] = g_score[tid];
    __syncthreads();
    for (int s = 64; s > 0; s >>= 1) {
        if (tid < s) red[tid] = fmaxf(red[tid], red[tid + s]);
        __syncthreads();
    }
    float m = red[0];
    __syncthreads();
    if (tid < 128) { float e = __expf(g_score[tid] - m); al[tid] = e; red[tid] = e; }
    __syncthreads();
    for (int s = 64; s > 0; s >>= 1) {
        if (tid < s) red[tid] += red[tid + s];
        __syncthreads();
    }
    float inv = __fdividef(1.f, red[0]);
    float o = 0.f;
#pragma unroll 8
    for (int p = 0; p < 128; p++) o += al[p] * g_ctx[p * 256 + tid];
    cat[256 + tid] = o * inv;
    __syncthreads();
    float acc = d1b[tid];
#pragma unroll 8
    for (int k = 0; k < 512; k++) acc += cat[k] * g_d1wT[k * 256 + tid];
    __syncthreads();
    g_u[tid] = acc;
}

__global__ void __launch_bounds__(256) final_kernel(const float* __restrict__ d2w,
                                                    const float* __restrict__ d2b,
                                                    float* __restrict__ out) {
    __shared__ float red[256];
    int tid = threadIdx.x;
    red[tid] = fmaxf(g_u[tid], 0.f) * d2w[tid];
    __syncthreads();
    for (int s = 128; s > 0; s >>= 1) {
        if (tid < s) red[tid] += red[tid + s];
        __syncthreads();
    }
    if (tid == 0) out[0] = __fdividef(1.f, 1.f + __expf(-(red[0] + d2b[0])));
}

// ---------------- launch ------------------------------------------------------
extern "C" void kernel_launch(void* const* d_in, const int* in_sizes, int n_in,
                              void* d_out, int out_size) {
    const int*   path   = (const int*)  d_in[0];
    const int*   query  = (const int*)  d_in[1];
    const float* embA   = (const float*)d_in[2];
    const float* embB   = (const float*)d_in[3];
    const float* conv_w = (const float*)d_in[4];
    const float* conv_b = (const float*)d_in[5];
    const float* wihf   = (const float*)d_in[6];
    const float* whhf   = (const float*)d_in[7];
    const float* bihf   = (const float*)d_in[8];
    const float* bhhf   = (const float*)d_in[9];
    const float* wihb   = (const float*)d_in[10];
    const float* whhb   = (const float*)d_in[11];
    const float* bihb   = (const float*)d_in[12];
    const float* bhhb   = (const float*)d_in[13];
    const float* d1w    = (const float*)d_in[14];
    const float* d1b    = (const float*)d_in[15];
    const float* d2w    = (const float*)d_in[16];
    const float* d2b    = (const float*)d_in[17];
    float* out = (float*)d_out;

    const int mma_smem = 2 * 128 * SROW * 2;           // 69632 B
    cudaFuncSetAttribute(gemm_kernel, cudaFuncAttributeMaxDynamicSharedMemorySize, mma_smem);
    cudaFuncSetAttribute(convgemm_kernel, cudaFuncAttributeMaxDynamicSharedMemorySize, mma_smem);

    setup_kernel<<<PREP_BLKS + 32768 + 1, 256>>>(path, query, embA, embB, conv_w, d1w,
                                                 wihf, wihb, bihf, bhhf, bihb, bhhb);
    convgemm_kernel<<<510, 256, mma_smem>>>(conv_b);
    gemm_kernel<<<dim3(509, 8), 256, mma_smem>>>();
    lstm_kernel<<<64, 512>>>(whhf, whhb);
    for (int it = 0; it < 2; it++) {
        att1_kernel<<<128, 256>>>(d1b, d2w, d2b);
        att2_kernel<<<1, 256>>>(d1b);
    }
    final_kernel<<<1, 256>>>(d2w, d2b, out);
}

// round 7
// speedup vs baseline: 3.2206x; 1.0543x over previous
#include <cuda_runtime.h>
#include <cuda_fp16.h>
#include <math.h>

#define Pn 128
#define Ln 512
#define En 256
#define Fn 128
#define Tn 509
#define SROW 136   // halves per smem row (272 B: ldmatrix conflict-free)

// ---------------- scratch (device globals; allocation is forbidden) ----------
__device__ __half  g_emb[(size_t)Pn * Ln * En];    // fp16 embedded tokens [p][l][e]
__device__ __half  g_conv[(size_t)Pn * 510 * Fn];  // conv+relu output [p][t'][f]
__device__ __half  g_gxh[(size_t)Pn * Tn * 1024];  // input gates fp16 [p*T][fwd512|bwd512]
__device__ float   g_ctx[Pn * En];                 // BiLSTM context [p][2H]
__device__ __half  g_cwh[Fn * 768];                // conv weights [f][w*256+e] fp16
__device__ float   g_d1wT[512 * 256];              // d1_w transposed [k][e]
__device__ __half  g_wh [1024 * 128];              // W_ih fp16 [n(fwd512|bwd512)][k]
__device__ float   g_bias[1024];                   // combined b_ih + b_hh
__device__ float   g_score[Pn];
__device__ float   g_u[En];

// ---------------- helpers ----------------------------------------------------
__device__ __forceinline__ float sigf(float x) {
    return __fdividef(1.f, 1.f + __expf(-x));
}
__device__ __forceinline__ float tanh_(float x) {
    return __fdividef(2.f, 1.f + __expf(-2.f * x)) - 1.f;
}
// HW tanh (sm_75+), ~5e-4 abs err — used only inside the LSTM recurrence
__device__ __forceinline__ float tanha(float x) {
    float y;
    asm("tanh.approx.f32 %0, %1;" : "=f"(y) : "f"(x));
    return y;
}
__device__ __forceinline__ float siga(float x) {
    return fmaf(0.5f, tanha(0.5f * x), 0.5f);
}
union UH2 { unsigned int u; __half2 h; };
__device__ __forceinline__ unsigned h2u(__half2 h) { UH2 v; v.h = h; return v.u; }

__device__ __forceinline__ void ldm_x4(unsigned& r0, unsigned& r1, unsigned& r2, unsigned& r3,
                                       unsigned addr) {
    asm volatile("ldmatrix.sync.aligned.m8n8.x4.shared.b16 {%0,%1,%2,%3}, [%4];"
                 : "=r"(r0), "=r"(r1), "=r"(r2), "=r"(r3) : "r"(addr));
}
__device__ __forceinline__ void mma16816(float* c, const unsigned* a, unsigned b0, unsigned b1) {
    asm volatile("mma.sync.aligned.m16n8k16.row.col.f32.f16.f16.f32 "
                 "{%0,%1,%2,%3}, {%4,%5,%6,%7}, {%8,%9}, {%0,%1,%2,%3};"
                 : "+f"(c[0]), "+f"(c[1]), "+f"(c[2]), "+f"(c[3])
                 : "r"(a[0]), "r"(a[1]), "r"(a[2]), "r"(a[3]), "r"(b0), "r"(b1));
}

// ---------------- launch 1: setup (prep + init_u + embed fused) ---------------
#define PREP_BLKS 1412
__global__ void __launch_bounds__(256) setup_kernel(
        const int* __restrict__ path, const int* __restrict__ query,
        const float* __restrict__ embA, const float* __restrict__ embB,
        const float* __restrict__ conv_w, const float* __restrict__ d1w,
        const float* __restrict__ wihf, const float* __restrict__ wihb,
        const float* __restrict__ bihf, const float* __restrict__ bhhf,
        const float* __restrict__ bihb, const float* __restrict__ bhhb) {
    int bx = blockIdx.x;
    if (bx < PREP_BLKS) {
        int idx = bx * 256 + threadIdx.x;
        if (idx < 98304) {                        // cwh[f][w*256+e] = conv_w[f][e][w]
            int f = idx / 768, r = idx - f * 768;
            int w = r >> 8, e = r & 255;
            g_cwh[idx] = __float2half(conv_w[(size_t)f * 768 + e * 3 + w]);
        } else if (idx < 98304 + 131072) {        // d1wT[k*256+e]
            int j = idx - 98304;
            int e = j & 255, k = j >> 8;
            g_d1wT[j] = d1w[(size_t)e * 512 + k];
        } else if (idx < 229376 + 131072) {       // g_wh[n][k] fp16
            int j = idx - 229376;
            int k = j & 127, n = j >> 7;
            float w = (n < 512) ? wihf[(size_t)n * 128 + k] : wihb[(size_t)(n - 512) * 128 + k];
            g_wh[j] = __float2half(w);
        } else if (idx < 360448 + 1024) {         // g_bias[n]
            int n = idx - 360448;
            g_bias[n] = (n < 512) ? (bihf[n] + bhhf[n]) : (bihb[n - 512] + bhhb[n - 512]);
        }
    } else if (bx < PREP_BLKS + 32768) {          // embedding gather
        int b = bx - PREP_BLKS;
        int p = b >> 8;
        int l = (b & 255) * 2 + (threadIdx.x >> 7);
        int t = threadIdx.x & 127;
        int tok = path[p * Ln + l];
        float2 v = *(const float2*)(embA + (size_t)tok * En + 2 * t);
        *(__half2*)(g_emb + ((size_t)p * Ln + l) * En + 2 * t) = __float22half2_rn(v);
    } else {                                      // init u
        g_u[threadIdx.x] = embB[(size_t)query[0] * En + threadIdx.x];
    }
}

// ---------------- launch 2: conv as GEMM (tensor cores) -----------------------
__global__ void __launch_bounds__(256) convgemm_kernel(const float* __restrict__ conv_b) {
    extern __shared__ __half smh[];
    __half* As = smh;                 // [128 m][SROW]
    __half* Bs = smh + 128 * SROW;    // [128 f][SROW]
    __shared__ float bias_s[128];

    int row0 = blockIdx.x * 128;
    int tid  = threadIdx.x;
    int wid  = tid >> 5, lane = tid & 31;
    int m0 = (wid >> 2) * 64;
    int n0 = (wid & 3) * 32;

    if (tid < 128) bias_s[tid] = conv_b[tid];

    unsigned sbase = (unsigned)__cvta_generic_to_shared(smh);
    unsigned aAddr[4], bAddr[2];
#pragma unroll
    for (int mi = 0; mi < 4; mi++) {
        int r = m0 + mi * 16 + (lane & 15);
        int ch = (lane >> 4) * 8;
        aAddr[mi] = sbase + (r * SROW + ch) * 2;
    }
#pragma unroll
    for (int bj = 0; bj < 2; bj++) {
        int r = n0 + bj * 16 + (lane & 7) + ((lane >> 4) << 3);
        int ch = ((lane >> 3) & 1) * 8;
        bAddr[bj] = sbase + (128 * SROW + r * SROW + ch) * 2;
    }

    float acc[4][4][4];
#pragma unroll
    for (int mi = 0; mi < 4; mi++)
#pragma unroll
        for (int nj = 0; nj < 4; nj++)
#pragma unroll
            for (int q = 0; q < 4; q++) acc[mi][nj][q] = 0.f;

    for (int kt = 0; kt < 6; kt++) {
        int k0 = kt * 128;
        if (kt) __syncthreads();
        for (int idx = tid; idx < 2048; idx += 256) {
            int rr = idx >> 4, c = idx & 15;
            int gr = row0 + rr;
            int p = gr / 510, t = gr - p * 510;
            const uint4* asrc = (const uint4*)(g_emb + ((size_t)p * Ln + t) * En + k0);
            *(uint4*)(As + rr * SROW + c * 8) = asrc[c];
            const uint4* bsrc = (const uint4*)(g_cwh + (size_t)rr * 768 + k0);
            *(uint4*)(Bs + rr * SROW + c * 8) = bsrc[c];
        }
        __syncthreads();

#pragma unroll
        for (int ks = 0; ks < 8; ks++) {
            unsigned a[4][4], b[2][4];
#pragma unroll
            for (int mi = 0; mi < 4; mi++)
                ldm_x4(a[mi][0], a[mi][1], a[mi][2], a[mi][3], aAddr[mi] + ks * 32);
#pragma unroll
            for (int bj = 0; bj < 2; bj++)
                ldm_x4(b[bj][0], b[bj][1], b[bj][2], b[bj][3], bAddr[bj] + ks * 32);
#pragma unroll
            for (int mi = 0; mi < 4; mi++)
#pragma unroll
                for (int nj = 0; nj < 4; nj++)
                    mma16816(acc[mi][nj], a[mi], b[nj >> 1][(nj & 1) * 2], b[nj >> 1][(nj & 1) * 2 + 1]);
        }
    }

    int qr = lane >> 2, qc = (lane & 3) * 2;
#pragma unroll
    for (int mi = 0; mi < 4; mi++) {
#pragma unroll
        for (int nj = 0; nj < 4; nj++) {
            int cc = n0 + nj * 8 + qc;
            float bx = bias_s[cc], by = bias_s[cc + 1];
            int r1 = row0 + m0 + mi * 16 + qr;
            __half2 v0 = __floats2half2_rn(fmaxf(acc[mi][nj][0] + bx, 0.f),
                                           fmaxf(acc[mi][nj][1] + by, 0.f));
            *(__half2*)(g_conv + (size_t)r1 * 128 + cc) = v0;
            __half2 v1 = __floats2half2_rn(fmaxf(acc[mi][nj][2] + bx, 0.f),
                                           fmaxf(acc[mi][nj][3] + by, 0.f));
            *(__half2*)(g_conv + (size_t)(r1 + 8) * 128 + cc) = v1;
        }
    }
}

// ---------------- launch 3: input-gate GEMM (pool fused into A-load) ----------
__global__ void __launch_bounds__(256) gemm_kernel() {
    extern __shared__ __half smh[];
    __half* As = smh;                 // [128 m][SROW]
    __half* Bs = smh + 128 * SROW;    // [128 n][SROW]
    __shared__ float bias_s[128];

    int row0 = blockIdx.x * 128;
    int col0 = blockIdx.y * 128;
    int tid  = threadIdx.x;
    int wid  = tid >> 5, lane = tid & 31;
    int m0 = (wid >> 2) * 64;
    int n0 = (wid & 3) * 32;

    if (tid < 128) bias_s[tid] = g_bias[col0 + tid];

    {
        const uint4* bsrc = (const uint4*)(g_wh + (size_t)col0 * 128);
        for (int idx = tid; idx < 2048; idx += 256) {
            int r = idx >> 4, c = idx & 15;
            int gr = row0 + r;
            int p = gr / Tn, t = gr - p * Tn;
            const uint4* csrc = (const uint4*)(g_conv + ((size_t)p * 510 + t) * 128);
            uint4 x = csrc[c], y = csrc[c + 16];
            UH2 ax, ay, r0, r1, r2, r3;
            ax.u = x.x; ay.u = y.x; r0.h = __hmax2(ax.h, ay.h);
            ax.u = x.y; ay.u = y.y; r1.h = __hmax2(ax.h, ay.h);
            ax.u = x.z; ay.u = y.z; r2.h = __hmax2(ax.h, ay.h);
            ax.u = x.w; ay.u = y.w; r3.h = __hmax2(ax.h, ay.h);
            uint4 m4 = make_uint4(r0.u, r1.u, r2.u, r3.u);
            *(uint4*)(As + r * SROW + c * 8) = m4;
            *(uint4*)(Bs + r * SROW + c * 8) = bsrc[r * 16 + c];
        }
    }
    __syncthreads();

    unsigned sbase = (unsigned)__cvta_generic_to_shared(smh);
    unsigned aAddr[4], bAddr[2];
#pragma unroll
    for (int mi = 0; mi < 4; mi++) {
        int r = m0 + mi * 16 + (lane & 15);
        int ch = (lane >> 4) * 8;
        aAddr[mi] = sbase + (r * SROW + ch) * 2;
    }
#pragma unroll
    for (int bj = 0; bj < 2; bj++) {
        int r = n0 + bj * 16 + (lane & 7) + ((lane >> 4) << 3);
        int ch = ((lane >> 3) & 1) * 8;
        bAddr[bj] = sbase + (128 * SROW + r * SROW + ch) * 2;
    }

    float acc[4][4][4];
#pragma unroll
    for (int mi = 0; mi < 4; mi++)
#pragma unroll
        for (int nj = 0; nj < 4; nj++)
#pragma unroll
            for (int q = 0; q < 4; q++) acc[mi][nj][q] = 0.f;

#pragma unroll
    for (int ks = 0; ks < 8; ks++) {
        unsigned a[4][4], b[2][4];
#pragma unroll
        for (int mi = 0; mi < 4; mi++)
            ldm_x4(a[mi][0], a[mi][1], a[mi][2], a[mi][3], aAddr[mi] + ks * 32);
#pragma unroll
        for (int bj = 0; bj < 2; bj++)
            ldm_x4(b[bj][0], b[bj][1], b[bj][2], b[bj][3], bAddr[bj] + ks * 32);
#pragma unroll
        for (int mi = 0; mi < 4; mi++)
#pragma unroll
            for (int nj = 0; nj < 4; nj++)
                mma16816(acc[mi][nj], a[mi], b[nj >> 1][(nj & 1) * 2], b[nj >> 1][(nj & 1) * 2 + 1]);
    }

    int qr = lane >> 2, qc = (lane & 3) * 2;
#pragma unroll
    for (int mi = 0; mi < 4; mi++) {
#pragma unroll
        for (int nj = 0; nj < 4; nj++) {
            int cc = n0 + nj * 8 + qc;
            float bx = bias_s[cc], by = bias_s[cc + 1];
            size_t base = (size_t)(row0 + m0 + mi * 16 + qr) * 1024 + col0 + cc;
            *(__half2*)(g_gxh + base) = __floats2half2_rn(acc[mi][nj][0] + bx, acc[mi][nj][1] + by);
            *(__half2*)(g_gxh + base + 8 * 1024) = __floats2half2_rn(acc[mi][nj][2] + bx, acc[mi][nj][3] + by);
        }
    }
}

// ---------------- launch 4: LSTM recurrence (tensor cores, 2 paths/CTA) -------
// 128 CTAs: bid = (pg<<1)|dir; paths pg*2, pg*2+1; 512 threads (16 warps).
// A (W_hh) register-resident; B from hN via ldmatrix (rows 2-7 stay zero).
// Pointwise on threads 0-255: (u = tid>>1, p = tid&1); HW tanh.approx.
__global__ void __launch_bounds__(512, 1) lstm_kernel(const float* __restrict__ whhf,
                                                      const float* __restrict__ whhb) {
    __shared__ float pre[512][10];               // 20 KB, conflict-free reads
    __shared__ __align__(16) __half hN[8][136];  // [path-slot][unit]

    int bid = blockIdx.x;
    int dir = bid & 1;
    int pg  = bid >> 1;
    int tid = threadIdx.x;
    int w   = tid >> 5, l = tid & 31;

    const float* whh = dir ? whhb : whhf;

    // A fragments: warp w owns gate-rows [w*32, w*32+32): 2 m16 tiles x 8 k-chunks
    unsigned A[2][8][4];
    int rbase = w * 32;
#pragma unroll
    for (int mt = 0; mt < 2; mt++)
#pragma unroll
        for (int kc = 0; kc < 8; kc++) {
            int r = rbase + mt * 16 + (l >> 2);
            int k = kc * 16 + (l & 3) * 2;
            float2 v0 = *(const float2*)(whh + (size_t)r * 128 + k);
            float2 v1 = *(const float2*)(whh + (size_t)(r + 8) * 128 + k);
            float2 v2 = *(const float2*)(whh + (size_t)r * 128 + k + 8);
            float2 v3 = *(const float2*)(whh + (size_t)(r + 8) * 128 + k + 8);
            A[mt][kc][0] = h2u(__float22half2_rn(v0));
            A[mt][kc][1] = h2u(__float22half2_rn(v1));
            A[mt][kc][2] = h2u(__float22half2_rn(v2));
            A[mt][kc][3] = h2u(__float22half2_rn(v3));
        }

    // zero hN (rows 2-7 remain zero forever)
    if (tid < 544) ((__half2*)&hN[0][0])[tid] = __float2half2_rn(0.f);

    bool act = tid < 256;
    int u = tid >> 1, p = tid & 1;
    int pathg = pg * 2 + p;
    long stride = dir ? -1024 : 1024;
    const __half* gp = g_gxh + (size_t)(act ? pathg : 0) * Tn * 1024 + dir * 512 + (act ? u : 0)
                     + (dir ? (size_t)(Tn - 1) * 1024 : 0);
    float gi = 0.f, gf = 0.f, gg = 0.f, go = 0.f;
    if (act) {
        gi = __half2float(gp[0]);   gf = __half2float(gp[128]);
        gg = __half2float(gp[256]); go = __half2float(gp[384]);
    }

    float c = 0.f, hval = 0.f;
    unsigned sb = (unsigned)__cvta_generic_to_shared(&hN[0][0]);
    unsigned ldaddr_base = sb + ((l & 7) * 136 + (l >> 3) * 8) * 2;

    __syncthreads();

    for (int s = 0; s < Tn; s++) {
        // prefetch next step's gx
        const __half* gn = gp + ((s + 1 < Tn) ? stride : 0);
        float ni = 0.f, nf = 0.f, ng = 0.f, no_ = 0.f;
        if (act) {
            ni = __half2float(gn[0]);   nf = __half2float(gn[128]);
            ng = __half2float(gn[256]); no_ = __half2float(gn[384]);
        }

        unsigned b[8][2];
#pragma unroll
        for (int ks = 0; ks < 4; ks++) {
            unsigned r0, r1, r2, r3;
            ldm_x4(r0, r1, r2, r3, ldaddr_base + ks * 64);
            b[2 * ks][0] = r0;     b[2 * ks][1] = r1;
            b[2 * ks + 1][0] = r2; b[2 * ks + 1][1] = r3;
        }
        // split accumulation: 4 chains of 4 MMAs each
        float C0a[4] = {0.f, 0.f, 0.f, 0.f}, C0b[4] = {0.f, 0.f, 0.f, 0.f};
        float C1a[4] = {0.f, 0.f, 0.f, 0.f}, C1b[4] = {0.f, 0.f, 0.f, 0.f};
#pragma unroll
        for (int kc = 0; kc < 4; kc++) {
            mma16816(C0a, A[0][kc], b[kc][0], b[kc][1]);
            mma16816(C1a, A[1][kc], b[kc][0], b[kc][1]);
            mma16816(C0b, A[0][kc + 4], b[kc + 4][0], b[kc + 4][1]);
            mma16816(C1b, A[1][kc + 4], b[kc + 4][0], b[kc + 4][1]);
        }

        {
            int rr = rbase + (l >> 2), cc = (l & 3) * 2;
            *(float2*)&pre[rr][cc]      = make_float2(C0a[0] + C0b[0], C0a[1] + C0b[1]);
            *(float2*)&pre[rr + 8][cc]  = make_float2(C0a[2] + C0b[2], C0a[3] + C0b[3]);
            *(float2*)&pre[rr + 16][cc] = make_float2(C1a[0] + C1b[0], C1a[1] + C1b[1]);
            *(float2*)&pre[rr + 24][cc] = make_float2(C1a[2] + C1b[2], C1a[3] + C1b[3]);
        }
        __syncthreads();

        if (act) {
            float iv = siga (gi + pre[u][p]);
            float fv = siga (gf + pre[128 + u][p]);
            float gv = tanha(gg + pre[256 + u][p]);
            float ov = siga (go + pre[384 + u][p]);
            c = fv * c + iv * gv;
            hval = ov * tanha(c);
            hN[p][u] = __float2half(hval);
        }

        gi = ni; gf = nf; gg = ng; go = no_;
        gp = gn;
        __syncthreads();
    }
    if (act) g_ctx[pathg * 256 + dir * 128 + u] = hval;
}

// ---------------- attention --------------------------------------------------
__global__ void __launch_bounds__(256) att1_kernel(const float* __restrict__ d1b,
                                                   const float* __restrict__ d2w,
                                                   const float* __restrict__ d2b) {
    __shared__ float cat[512];
    __shared__ float red[256];
    int p = blockIdx.x, tid = threadIdx.x;
    cat[tid]       = g_ctx[p * 256 + tid];
    cat[256 + tid] = g_u[tid];
    __syncthreads();
    float acc = d1b[tid];
#pragma unroll 8
    for (int k = 0; k < 512; k++) acc += cat[k] * g_d1wT[k * 256 + tid];
    red[tid] = tanh_(acc) * d2w[tid];
    __syncthreads();
    for (int s = 128; s > 0; s >>= 1) {
        if (tid < s) red[tid] += red[tid + s];
        __syncthreads();
    }
    if (tid == 0) g_score[p] = red[0] + d2b[0];
}

__global__ void __launch_bounds__(256) att2_kernel(const float* __restrict__ d1b) {
    __shared__ float al[128];
    __shared__ float red[128];
    __shared__ float cat[512];
    int tid = threadIdx.x;
    cat[tid] = g_u[tid];
    if (tid < 128) red[tid] = g_score[tid];
    __syncthreads();
    for (int s = 64; s > 0; s >>= 1) {
        if (tid < s) red[tid] = fmaxf(red[tid], red[tid + s]);
        __syncthreads();
    }
    float m = red[0];
    __syncthreads();
    if (tid < 128) { float e = __expf(g_score[tid] - m); al[tid] = e; red[tid] = e; }
    __syncthreads();
    for (int s = 64; s > 0; s >>= 1) {
        if (tid < s) red[tid] += red[tid + s];
        __syncthreads();
    }
    float inv = __fdividef(1.f, red[0]);
    float o = 0.f;
#pragma unroll 8
    for (int p = 0; p < 128; p++) o += al[p] * g_ctx[p * 256 + tid];
    cat[256 + tid] = o * inv;
    __syncthreads();
    float acc = d1b[tid];
#pragma unroll 8
    for (int k = 0; k < 512; k++) acc += cat[k] * g_d1wT[k * 256 + tid];
    __syncthreads();
    g_u[tid] = acc;
}

__global__ void __launch_bounds__(256) final_kernel(const float* __restrict__ d2w,
                                                    const float* __restrict__ d2b,
                                                    float* __restrict__ out) {
    __shared__ float red[256];
    int tid = threadIdx.x;
    red[tid] = fmaxf(g_u[tid], 0.f) * d2w[tid];
    __syncthreads();
    for (int s = 128; s > 0; s >>= 1) {
        if (tid < s) red[tid] += red[tid + s];
        __syncthreads();
    }
    if (tid == 0) out[0] = __fdividef(1.f, 1.f + __expf(-(red[0] + d2b[0])));
}

// ---------------- launch ------------------------------------------------------
extern "C" void kernel_launch(void* const* d_in, const int* in_sizes, int n_in,
                              void* d_out, int out_size) {
    const int*   path   = (const int*)  d_in[0];
    const int*   query  = (const int*)  d_in[1];
    const float* embA   = (const float*)d_in[2];
    const float* embB   = (const float*)d_in[3];
    const float* conv_w = (const float*)d_in[4];
    const float* conv_b = (const float*)d_in[5];
    const float* wihf   = (const float*)d_in[6];
    const float* whhf   = (const float*)d_in[7];
    const float* bihf   = (const float*)d_in[8];
    const float* bhhf   = (const float*)d_in[9];
    const float* wihb   = (const float*)d_in[10];
    const float* whhb   = (const float*)d_in[11];
    const float* bihb   = (const float*)d_in[12];
    const float* bhhb   = (const float*)d_in[13];
    const float* d1w    = (const float*)d_in[14];
    const float* d1b    = (const float*)d_in[15];
    const float* d2w    = (const float*)d_in[16];
    const float* d2b    = (const float*)d_in[17];
    float* out = (float*)d_out;

    const int mma_smem = 2 * 128 * SROW * 2;           // 69632 B
    cudaFuncSetAttribute(gemm_kernel, cudaFuncAttributeMaxDynamicSharedMemorySize, mma_smem);
    cudaFuncSetAttribute(convgemm_kernel, cudaFuncAttributeMaxDynamicSharedMemorySize, mma_smem);

    setup_kernel<<<PREP_BLKS + 32768 + 1, 256>>>(path, query, embA, embB, conv_w, d1w,
                                                 wihf, wihb, bihf, bhhf, bihb, bhhb);
    convgemm_kernel<<<510, 256, mma_smem>>>(conv_b);
    gemm_kernel<<<dim3(509, 8), 256, mma_smem>>>();
    lstm_kernel<<<128, 512>>>(whhf, whhb);
    for (int it = 0; it < 2; it++) {
        att1_kernel<<<128, 256>>>(d1b, d2w, d2b);
        att2_kernel<<<1, 256>>>(d1b);
    }
    final_kernel<<<1, 256>>>(d2w, d2b, out);
}